// round 12
// baseline (speedup 1.0000x reference)
#include <cuda_runtime.h>
#include <cuda_bf16.h>
#include <math.h>
#include <stdint.h>

#define BATCH 8
#define SEQ   2048
#define EMB   1024
#define HEAD  128
#define NTRI  136            // lower-tri 128x128 tiles per batch
#define SCALE 0.03125f       // 1/sqrt(1024)

typedef unsigned short ushort_t;

// Stage geometry (block tile 128x128, K-chunk 16):
//   slab = 128 rows x 48B (16 data ushorts + 8 pad) = 6144B, conflict-free for ldmatrix
//   stage = Ah,Al,Bh,Bl slabs = 24576B; ring of 4 stages.
#define ROWB   48u
#define SLAB   6144u
#define STAGE  24576u

// ---------------- global scratch: pre-split bf16 hi/lo arrays -------------------
__device__ ushort_t g_xh[BATCH * SEQ * EMB], g_xl[BATCH * SEQ * EMB];     // X split [row][emb]
__device__ ushort_t g_wth[3 * HEAD * EMB],   g_wtl[3 * HEAD * EMB];       // W^T split [mat][head][emb]
__device__ ushort_t g_qh[BATCH * SEQ * HEAD], g_ql[BATCH * SEQ * HEAD];   // q' split [tok][head]
__device__ ushort_t g_kh[BATCH * SEQ * HEAD], g_kl[BATCH * SEQ * HEAD];   // k  split [tok][head]
__device__ ushort_t g_vth[BATCH * HEAD * SEQ], g_vtl[BATCH * HEAD * SEQ]; // (v*inv)^T split [head][key]
__device__ ushort_t g_eh[(size_t)BATCH * SEQ * SEQ];                      // expS hi [q][key] 64MB
__device__ ushort_t g_el[(size_t)BATCH * SEQ * SEQ];                      // expS lo 64MB
__device__ float    g_v[BATCH * SEQ * HEAD];
__device__ float    g_colsum[BATCH * SEQ];

// ---------------- helpers ------------------------------------------------------
__device__ __forceinline__ uint32_t smem_u32(const void* p) {
    uint32_t a;
    asm("{ .reg .u64 t; cvta.to.shared.u64 t, %1; cvt.u32.u64 %0, t; }" : "=r"(a) : "l"(p));
    return a;
}
__device__ __forceinline__ void cpa16(uint32_t dst, const void* src) {
    asm volatile("cp.async.cg.shared.global [%0], [%1], 16;" :: "r"(dst), "l"(src));
}
__device__ __forceinline__ float fast_exp(float x) {
    float r = 2.0876757e-9f;
    r = fmaf(r, x, 2.5052108e-8f);
    r = fmaf(r, x, 2.7557319e-7f);
    r = fmaf(r, x, 2.7557319e-6f);
    r = fmaf(r, x, 2.4801587e-5f);
    r = fmaf(r, x, 1.9841270e-4f);
    r = fmaf(r, x, 1.3888889e-3f);
    r = fmaf(r, x, 8.3333333e-3f);
    r = fmaf(r, x, 4.1666667e-2f);
    r = fmaf(r, x, 1.6666667e-1f);
    r = fmaf(r, x, 0.5f);
    r = fmaf(r, x, 1.0f);
    r = fmaf(r, x, 1.0f);
    if (fabsf(x) > 2.0f) r = __expf(x);
    return r;
}
__device__ __forceinline__ void tri_decode(int t, int& qt, int& kt) {
    int q = (int)((sqrtf(8.0f * (float)t + 1.0f) - 1.0f) * 0.5f);
    while ((q + 1) * (q + 2) / 2 <= t) q++;
    while (q * (q + 1) / 2 > t) q--;
    qt = q;
    kt = t - q * (q + 1) / 2;
}
__device__ __forceinline__ void split2(float x, ushort_t& h, ushort_t& l) {
    __nv_bfloat16 bh = __float2bfloat16_rn(x);
    float r = x - __bfloat162float(bh);
    __nv_bfloat16 bl = __float2bfloat16_rn(r);
    h = *(ushort_t*)&bh;
    l = *(ushort_t*)&bl;
}
__device__ __forceinline__ void splitpack(float x0, float x1, unsigned& hh, unsigned& ll) {
    ushort_t h0, l0, h1, l1;
    split2(x0, h0, l0);
    split2(x1, h1, l1);
    hh = (unsigned)h0 | ((unsigned)h1 << 16);
    ll = (unsigned)l0 | ((unsigned)l1 << 16);
}
__device__ __forceinline__ void mma16816(float c[4], const unsigned a[4], const unsigned b[2]) {
    asm volatile(
        "mma.sync.aligned.m16n8k16.row.col.f32.bf16.bf16.f32 "
        "{%0,%1,%2,%3}, {%4,%5,%6,%7}, {%8,%9}, {%0,%1,%2,%3};\n"
        : "+f"(c[0]), "+f"(c[1]), "+f"(c[2]), "+f"(c[3])
        : "r"(a[0]), "r"(a[1]), "r"(a[2]), "r"(a[3]), "r"(b[0]), "r"(b[1]));
}
__device__ __forceinline__ void ldsm_x4(unsigned* r, uint32_t a) {
    asm volatile("ldmatrix.sync.aligned.m8n8.x4.shared.b16 {%0,%1,%2,%3}, [%4];"
                 : "=r"(r[0]), "=r"(r[1]), "=r"(r[2]), "=r"(r[3]) : "r"(a));
}

// Issue one k16 stage: each thread copies one 16B piece per slab (row = tid>>1, half = tid&1).
__device__ __forceinline__ void stage_issue(
    uint32_t base, const ushort_t* Ah, const ushort_t* Al,
    const ushort_t* Bh, const ushort_t* Bl,
    size_t strideA, size_t strideB, int k0, int row, int half) {
    const uint32_t ro = (uint32_t)row * ROWB + (uint32_t)half * 16u;
    const size_t  go = (size_t)k0 + half * 8;
    cpa16(base + ro,            Ah + (size_t)row * strideA + go);
    cpa16(base + SLAB + ro,     Al + (size_t)row * strideA + go);
    cpa16(base + 2*SLAB + ro,   Bh + (size_t)row * strideB + go);
    cpa16(base + 3*SLAB + ro,   Bl + (size_t)row * strideB + go);
    asm volatile("cp.async.commit_group;");
}

// One staged k16: warp computes its 32x64 tile (R8 order, bit-identical math).
__device__ __forceinline__ void chunk_mma(uint32_t base, int lane, int wm, int wn,
                                          float c[2][8][4]) {
    const uint32_t aAddr = base + (uint32_t)(wm * 32 + (lane & 15)) * ROWB + ((lane >> 4) * 16u);
    unsigned ah[2][4], al[2][4];
    ldsm_x4(ah[0], aAddr);
    ldsm_x4(ah[1], aAddr + 16u * ROWB);
    ldsm_x4(al[0], aAddr + SLAB);
    ldsm_x4(al[1], aAddr + SLAB + 16u * ROWB);
#pragma unroll
    for (int j = 0; j < 4; j++) {
        const uint32_t bAddr = base + 2*SLAB
            + (uint32_t)(wn * 64 + j * 16 + (lane & 7) + (((lane >> 4) & 1) * 8)) * ROWB
            + (((lane >> 3) & 1) * 16u);
        unsigned bh4[4], bl4[4];
        ldsm_x4(bh4, bAddr);
        ldsm_x4(bl4, bAddr + SLAB);
#pragma unroll
        for (int nn = 0; nn < 2; nn++) {
            const int n = j * 2 + nn;
            unsigned bh2[2] = {bh4[nn * 2], bh4[nn * 2 + 1]};
            unsigned bl2[2] = {bl4[nn * 2], bl4[nn * 2 + 1]};
#pragma unroll
            for (int m = 0; m < 2; m++) {
                mma16816(c[m][n], ah[m], bh2);
                mma16816(c[m][n], al[m], bh2);
                mma16816(c[m][n], ah[m], bl2);
            }
        }
    }
}

// Pipelined tile GEMM over NC chunks of k=16. 4-stage ring, ONE sync per iteration.
// Safety: the stage written at iter i is (i-1)&3, consumed at iter i-1; the write is
// placed after iter i's __syncthreads, which every warp reaches only after finishing
// chunk_mma(i-1). Reads of stage i are covered by per-thread wait_group + the sync.
__device__ __forceinline__ void tile_gemm(
    uint32_t sb, const ushort_t* Ah, const ushort_t* Al,
    const ushort_t* Bh, const ushort_t* Bl,
    size_t strideA, size_t strideB, int NC, int tid, float c[2][8][4]) {
    const int lane = tid & 31, wid = tid >> 5;
    const int wm = wid & 3, wn = wid >> 2;
    const int row = tid >> 1, half = tid & 1;

    const int npro = (NC < 3) ? NC : 3;
    for (int p = 0; p < npro; p++)
        stage_issue(sb + (uint32_t)p * STAGE, Ah, Al, Bh, Bl, strideA, strideB, p * 16, row, half);

    for (int i = 0; i < NC; i++) {
        const int rem = NC - 1 - i;
        if (rem >= 2)      asm volatile("cp.async.wait_group 2;");
        else if (rem == 1) asm volatile("cp.async.wait_group 1;");
        else               asm volatile("cp.async.wait_group 0;");
        __syncthreads();
        if (i + 3 < NC)
            stage_issue(sb + (uint32_t)((i + 3) & 3) * STAGE, Ah, Al, Bh, Bl,
                        strideA, strideB, (i + 3) * 16, row, half);
        chunk_mma(sb + (uint32_t)(i & 3) * STAGE, lane, wm, wn, c);
    }
    __syncthreads();
}

// ---------------- kernel 0: zero -----------------------------------------------
__global__ void zero_kernel(float* __restrict__ out) {
    int i = blockIdx.x * blockDim.x + threadIdx.x;
    if (i < BATCH * SEQ * HEAD) out[i] = 0.0f;
    if (i < BATCH * SEQ) g_colsum[i] = 0.0f;
}

// ---------------- prep: split X ------------------------------------------------
__global__ __launch_bounds__(256) void prep_x(const float* __restrict__ X) {
    int p = blockIdx.x * 256 + threadIdx.x;
    int row = p >> 9, kp = (p & 511) * 2;
    float2 v = *(const float2*)(X + (size_t)row * EMB + kp);
    unsigned hh, ll;
    splitpack(v.x, v.y, hh, ll);
    *(unsigned*)&g_xh[(size_t)row * EMB + kp] = hh;
    *(unsigned*)&g_xl[(size_t)row * EMB + kp] = ll;
}

// ---------------- prep: split W^T ----------------------------------------------
__global__ __launch_bounds__(256) void prep_w(const float* __restrict__ Wq,
                                              const float* __restrict__ Wk,
                                              const float* __restrict__ Wv) {
    int p = blockIdx.x * 256 + threadIdx.x;
    int mat = p >> 16;
    int rem = p & 65535;
    int n = rem >> 9, kp = (rem & 511) * 2;
    const float* W = (mat == 0) ? Wq : (mat == 1) ? Wk : Wv;
    float v0 = W[(size_t)kp * HEAD + n];
    float v1 = W[(size_t)(kp + 1) * HEAD + n];
    unsigned hh, ll;
    splitpack(v0, v1, hh, ll);
    size_t off = (size_t)(mat * HEAD + n) * EMB + kp;
    *(unsigned*)&g_wth[off] = hh;
    *(unsigned*)&g_wtl[off] = ll;
}

// ---------------- kernel 1: QKV (128x128 tile) ---------------------------------
__global__ __launch_bounds__(256, 2) void qkv_tc(void) {
    extern __shared__ ushort_t dynS[];
    const int tid = threadIdx.x, lane = tid & 31, wid = tid >> 5;
    const int wm = wid & 3, wn = wid >> 2;
    const int rt = blockIdx.x, mat = blockIdx.y;
    const uint32_t sb = smem_u32(dynS);

    float c[2][8][4];
#pragma unroll
    for (int m = 0; m < 2; m++)
#pragma unroll
        for (int n = 0; n < 8; n++)
#pragma unroll
            for (int i = 0; i < 4; i++) c[m][n][i] = 0.0f;

    tile_gemm(sb,
              g_xh + (size_t)(rt * 128) * EMB, g_xl + (size_t)(rt * 128) * EMB,
              g_wth + (size_t)(mat * HEAD) * EMB, g_wtl + (size_t)(mat * HEAD) * EMB,
              EMB, EMB, 64, tid, c);

    const int gid = lane >> 2, tig = lane & 3;
    if (mat == 2) {
#pragma unroll
        for (int m = 0; m < 2; m++) {
            const int r = rt * 128 + wm * 32 + m * 16 + gid;
#pragma unroll
            for (int n = 0; n < 8; n++) {
                const int col = wn * 64 + n * 8 + tig * 2;
                *(float2*)(g_v + (size_t)r * HEAD + col)       = make_float2(c[m][n][0], c[m][n][1]);
                *(float2*)(g_v + (size_t)(r + 8) * HEAD + col) = make_float2(c[m][n][2], c[m][n][3]);
            }
        }
    } else {
        ushort_t* Yh = (mat == 0) ? g_qh : g_kh;
        ushort_t* Yl = (mat == 0) ? g_ql : g_kl;
        const float sc = (mat == 0) ? SCALE : 1.0f;
#pragma unroll
        for (int m = 0; m < 2; m++) {
            const int r = rt * 128 + wm * 32 + m * 16 + gid;
#pragma unroll
            for (int n = 0; n < 8; n++) {
                const int col = wn * 64 + n * 8 + tig * 2;
                unsigned hh, ll;
                splitpack(c[m][n][0] * sc, c[m][n][1] * sc, hh, ll);
                *(unsigned*)&Yh[(size_t)r * HEAD + col] = hh;
                *(unsigned*)&Yl[(size_t)r * HEAD + col] = ll;
                splitpack(c[m][n][2] * sc, c[m][n][3] * sc, hh, ll);
                *(unsigned*)&Yh[(size_t)(r + 8) * HEAD + col] = hh;
                *(unsigned*)&Yl[(size_t)(r + 8) * HEAD + col] = ll;
            }
        }
    }
}

// ---------------- kernel 2: scores (128x128 tile) ------------------------------
__global__ __launch_bounds__(256, 2) void scores_tc(void) {
    extern __shared__ ushort_t dynS[];
    __shared__ float s_col[128];
    const int tid = threadIdx.x, lane = tid & 31, wid = tid >> 5;
    const int wm = wid & 3, wn = wid >> 2;
    const int b = blockIdx.x / NTRI;
    int qt, kt;
    tri_decode(blockIdx.x % NTRI, qt, kt);
    const uint32_t sb = smem_u32(dynS);

    if (tid < 128) s_col[tid] = 0.0f;

    float c[2][8][4];
#pragma unroll
    for (int m = 0; m < 2; m++)
#pragma unroll
        for (int n = 0; n < 8; n++)
#pragma unroll
            for (int i = 0; i < 4; i++) c[m][n][i] = 0.0f;

    tile_gemm(sb,
              g_qh + (size_t)(b * SEQ + qt * 128) * HEAD, g_ql + (size_t)(b * SEQ + qt * 128) * HEAD,
              g_kh + (size_t)(b * SEQ + kt * 128) * HEAD, g_kl + (size_t)(b * SEQ + kt * 128) * HEAD,
              HEAD, HEAD, 8, tid, c);

    const int gid = lane >> 2, tig = lane & 3;
    float p0[8], p1[8];
#pragma unroll
    for (int n = 0; n < 8; n++) { p0[n] = 0.0f; p1[n] = 0.0f; }

#pragma unroll
    for (int m = 0; m < 2; m++) {
        const int r   = wm * 32 + m * 16 + gid;
        const int gq0 = qt * 128 + r;
        const int gq1 = gq0 + 8;
#pragma unroll
        for (int n = 0; n < 8; n++) {
            const int cn = wn * 64 + n * 8 + tig * 2;
            const int gk = kt * 128 + cn;
            float e0 = (gq0 >= gk)     ? fast_exp(c[m][n][0]) : 0.0f;
            float e1 = (gq0 >= gk + 1) ? fast_exp(c[m][n][1]) : 0.0f;
            float e2 = (gq1 >= gk)     ? fast_exp(c[m][n][2]) : 0.0f;
            float e3 = (gq1 >= gk + 1) ? fast_exp(c[m][n][3]) : 0.0f;
            p0[n] += e0 + e2;
            p1[n] += e1 + e3;
            unsigned hh, ll;
            size_t base0 = ((size_t)b * SEQ + gq0) * SEQ + gk;
            splitpack(e0, e1, hh, ll);
            *(unsigned*)&g_eh[base0] = hh;
            *(unsigned*)&g_el[base0] = ll;
            size_t base1 = ((size_t)b * SEQ + gq1) * SEQ + gk;
            splitpack(e2, e3, hh, ll);
            *(unsigned*)&g_eh[base1] = hh;
            *(unsigned*)&g_el[base1] = ll;
        }
    }
#pragma unroll
    for (int n = 0; n < 8; n++) {
        p0[n] += __shfl_down_sync(0xffffffff, p0[n], 16);
        p0[n] += __shfl_down_sync(0xffffffff, p0[n], 8);
        p0[n] += __shfl_down_sync(0xffffffff, p0[n], 4);
        p1[n] += __shfl_down_sync(0xffffffff, p1[n], 16);
        p1[n] += __shfl_down_sync(0xffffffff, p1[n], 8);
        p1[n] += __shfl_down_sync(0xffffffff, p1[n], 4);
    }
    if (lane < 4) {
#pragma unroll
        for (int n = 0; n < 8; n++) {
            atomicAdd(&s_col[wn * 64 + n * 8 + lane * 2],     p0[n]);
            atomicAdd(&s_col[wn * 64 + n * 8 + lane * 2 + 1], p1[n]);
        }
    }
    __syncthreads();
    if (tid < 128) atomicAdd(&g_colsum[b * SEQ + kt * 128 + tid], s_col[tid]);
}

// ---------------- kernel 3: vprep — (v*inv)^T split ----------------------------
__global__ __launch_bounds__(256) void vprep_kernel() {
    __shared__ ushort_t sh[128][72], sl[128][72];
    const int tid   = threadIdx.x;
    const int batch = blockIdx.x >> 5;
    const int kt64  = blockIdx.x & 31;

    const int r  = tid >> 2;
    const int cb = (tid & 3) * 32;
    const int key = batch * SEQ + kt64 * 64 + r;
    const float inv = 1.0f / g_colsum[key];
    const float* vp = g_v + (size_t)key * HEAD + cb;
#pragma unroll
    for (int j = 0; j < 8; j++) {
        float4 v4 = *(const float4*)(vp + j * 4);
        float v[4] = {v4.x, v4.y, v4.z, v4.w};
#pragma unroll
        for (int i = 0; i < 4; i++) {
            ushort_t h, l;
            split2(v[i] * inv, h, l);
            sh[cb + j * 4 + i][r] = h;
            sl[cb + j * 4 + i][r] = l;
        }
    }
    __syncthreads();
    const int h  = tid >> 1;
    const int kc = (tid & 1) * 32;
    size_t gbase = (size_t)(batch * HEAD + h) * SEQ + kt64 * 64 + kc;
#pragma unroll
    for (int j = 0; j < 4; j++) {
        uint2 u0 = *(const uint2*)&sh[h][kc + j * 8];
        uint2 u1 = *(const uint2*)&sh[h][kc + j * 8 + 4];
        *(uint4*)&g_vth[gbase + j * 8] = make_uint4(u0.x, u0.y, u1.x, u1.y);
        uint2 w0 = *(const uint2*)&sl[h][kc + j * 8];
        uint2 w1 = *(const uint2*)&sl[h][kc + j * 8 + 4];
        *(uint4*)&g_vtl[gbase + j * 8] = make_uint4(w0.x, w0.y, w1.x, w1.y);
    }
}

// ---------------- kernel 4: out = expS' @ v' (128x128 tile) --------------------
__global__ __launch_bounds__(256, 2) void out_tc(float* __restrict__ out) {
    extern __shared__ ushort_t dynS[];
    const int tid = threadIdx.x, lane = tid & 31, wid = tid >> 5;
    const int wm = wid & 3, wn = wid >> 2;
    const int b = blockIdx.x / NTRI;
    int qt, kt;
    tri_decode(blockIdx.x % NTRI, qt, kt);
    const uint32_t sb = smem_u32(dynS);

    float c[2][8][4];
#pragma unroll
    for (int m = 0; m < 2; m++)
#pragma unroll
        for (int n = 0; n < 8; n++)
#pragma unroll
            for (int i = 0; i < 4; i++) c[m][n][i] = 0.0f;

    tile_gemm(sb,
              g_eh + ((size_t)b * SEQ + qt * 128) * SEQ + kt * 128,
              g_el + ((size_t)b * SEQ + qt * 128) * SEQ + kt * 128,
              g_vth + (size_t)(b * HEAD) * SEQ + kt * 128,
              g_vtl + (size_t)(b * HEAD) * SEQ + kt * 128,
              SEQ, SEQ, 8, tid, c);

    const int gid = lane >> 2, tig = lane & 3;
#pragma unroll
    for (int m = 0; m < 2; m++) {
        const int r = qt * 128 + wm * 32 + m * 16 + gid;
#pragma unroll
        for (int n = 0; n < 8; n++) {
            const int cn = wn * 64 + n * 8 + tig * 2;
            float* op = out + ((size_t)b * SEQ + r) * HEAD + cn;
            atomicAdd(op,     c[m][n][0]);
            atomicAdd(op + 1, c[m][n][1]);
            atomicAdd(op + (size_t)8 * HEAD,     c[m][n][2]);
            atomicAdd(op + (size_t)8 * HEAD + 1, c[m][n][3]);
        }
    }
}

// ---------------- launch --------------------------------------------------------
extern "C" void kernel_launch(void* const* d_in, const int* in_sizes, int n_in,
                              void* d_out, int out_size) {
    const float* X  = (const float*)d_in[0];
    const float* Wq = (const float*)d_in[1];
    const float* Wk = (const float*)d_in[2];
    const float* Wv = (const float*)d_in[3];
    float* out = (float*)d_out;

    const int smem = 4 * STAGE;   // 98304
    cudaFuncSetAttribute(qkv_tc,    cudaFuncAttributeMaxDynamicSharedMemorySize, smem);
    cudaFuncSetAttribute(scores_tc, cudaFuncAttributeMaxDynamicSharedMemorySize, smem);
    cudaFuncSetAttribute(out_tc,    cudaFuncAttributeMaxDynamicSharedMemorySize, smem);

    zero_kernel<<<(BATCH * SEQ * HEAD + 255) / 256, 256>>>(out);
    prep_x<<<BATCH * SEQ * EMB / 2 / 256, 256>>>(X);
    prep_w<<<3 * HEAD * EMB / 2 / 256, 256>>>(Wq, Wk, Wv);
    qkv_tc<<<dim3(BATCH * SEQ / 128, 3), 256, smem>>>();
    scores_tc<<<BATCH * NTRI, 256, smem>>>();
    vprep_kernel<<<BATCH * SEQ / 64, 256>>>();
    out_tc<<<BATCH * NTRI, 256, smem>>>(out);
}

// round 13
// speedup vs baseline: 1.0964x; 1.0964x over previous
#include <cuda_runtime.h>
#include <cuda_bf16.h>
#include <math.h>
#include <stdint.h>

#define BATCH 8
#define SEQ   2048
#define EMB   1024
#define HEAD  128
#define NTRI  136            // lower-tri 128x128 tiles per batch
#define SCALE 0.03125f       // 1/sqrt(1024)

typedef unsigned short ushort_t;

// Stage geometry: 4 slabs of [128][40] ushort = 10240B each; stage = 40960B.
#define SLAB  10240u
#define STAGE 40960u

// ---------------- global scratch: pre-split bf16 hi/lo arrays -------------------
__device__ ushort_t g_xh[BATCH * SEQ * EMB], g_xl[BATCH * SEQ * EMB];     // X split [row][emb]
__device__ ushort_t g_wth[3 * HEAD * EMB],   g_wtl[3 * HEAD * EMB];       // W^T split [mat][head][emb]
__device__ ushort_t g_qh[BATCH * SEQ * HEAD], g_ql[BATCH * SEQ * HEAD];   // q' split [tok][head]
__device__ ushort_t g_kh[BATCH * SEQ * HEAD], g_kl[BATCH * SEQ * HEAD];   // k  split [tok][head]
__device__ ushort_t g_vth[BATCH * HEAD * SEQ], g_vtl[BATCH * HEAD * SEQ]; // (v*inv)^T split [head][key]
__device__ ushort_t g_eh[(size_t)BATCH * SEQ * SEQ];                      // expS hi [q][key] 64MB
__device__ ushort_t g_el[(size_t)BATCH * SEQ * SEQ];                      // expS lo 64MB
__device__ float    g_v[BATCH * SEQ * HEAD];
__device__ float    g_colsum[BATCH * SEQ];

// ---------------- helpers ------------------------------------------------------
__device__ __forceinline__ uint32_t smem_u32(const void* p) {
    uint32_t a;
    asm("{ .reg .u64 t; cvta.to.shared.u64 t, %1; cvt.u32.u64 %0, t; }" : "=r"(a) : "l"(p));
    return a;
}
__device__ __forceinline__ void cpa16(uint32_t dst, const void* src) {
    asm volatile("cp.async.cg.shared.global [%0], [%1], 16;" :: "r"(dst), "l"(src));
}
__device__ __forceinline__ float fast_exp(float x) {
    float r = 2.0876757e-9f;
    r = fmaf(r, x, 2.5052108e-8f);
    r = fmaf(r, x, 2.7557319e-7f);
    r = fmaf(r, x, 2.7557319e-6f);
    r = fmaf(r, x, 2.4801587e-5f);
    r = fmaf(r, x, 1.9841270e-4f);
    r = fmaf(r, x, 1.3888889e-3f);
    r = fmaf(r, x, 8.3333333e-3f);
    r = fmaf(r, x, 4.1666667e-2f);
    r = fmaf(r, x, 1.6666667e-1f);
    r = fmaf(r, x, 0.5f);
    r = fmaf(r, x, 1.0f);
    r = fmaf(r, x, 1.0f);
    if (fabsf(x) > 2.0f) r = __expf(x);
    return r;
}
__device__ __forceinline__ void tri_decode(int t, int& qt, int& kt) {
    int q = (int)((sqrtf(8.0f * (float)t + 1.0f) - 1.0f) * 0.5f);
    while ((q + 1) * (q + 2) / 2 <= t) q++;
    while (q * (q + 1) / 2 > t) q--;
    qt = q;
    kt = t - q * (q + 1) / 2;
}
__device__ __forceinline__ void split2(float x, ushort_t& h, ushort_t& l) {
    __nv_bfloat16 bh = __float2bfloat16_rn(x);
    float r = x - __bfloat162float(bh);
    __nv_bfloat16 bl = __float2bfloat16_rn(r);
    h = *(ushort_t*)&bh;
    l = *(ushort_t*)&bl;
}
__device__ __forceinline__ void splitpack(float x0, float x1, unsigned& hh, unsigned& ll) {
    ushort_t h0, l0, h1, l1;
    split2(x0, h0, l0);
    split2(x1, h1, l1);
    hh = (unsigned)h0 | ((unsigned)h1 << 16);
    ll = (unsigned)l0 | ((unsigned)l1 << 16);
}
__device__ __forceinline__ void mma16816(float c[4], const unsigned a[4], const unsigned b[2]) {
    asm volatile(
        "mma.sync.aligned.m16n8k16.row.col.f32.bf16.bf16.f32 "
        "{%0,%1,%2,%3}, {%4,%5,%6,%7}, {%8,%9}, {%0,%1,%2,%3};\n"
        : "+f"(c[0]), "+f"(c[1]), "+f"(c[2]), "+f"(c[3])
        : "r"(a[0]), "r"(a[1]), "r"(a[2]), "r"(a[3]), "r"(b[0]), "r"(b[1]));
}
__device__ __forceinline__ void ldsm_x4(unsigned* r, uint32_t a) {
    asm volatile("ldmatrix.sync.aligned.m8n8.x4.shared.b16 {%0,%1,%2,%3}, [%4];"
                 : "=r"(r[0]), "=r"(r[1]), "=r"(r[2]), "=r"(r[3]) : "r"(a));
}

// Issue one stage's cp.async loads: 4 slabs (Ah, Al, Bh, Bl), 2 rows x 16B per thread per slab.
__device__ __forceinline__ void stage_issue(
    uint32_t base, const ushort_t* Ah, const ushort_t* Al,
    const ushort_t* Bh, const ushort_t* Bl,
    size_t strideA, size_t strideB, int k0, int r0, int seg) {
    const uint32_t ro = (uint32_t)r0 * 80u + (uint32_t)seg * 2u;
    cpa16(base + ro,                  Ah + (size_t)r0 * strideA + k0 + seg);
    cpa16(base + ro + 5120u,          Ah + (size_t)(r0 + 64) * strideA + k0 + seg);
    cpa16(base + SLAB + ro,           Al + (size_t)r0 * strideA + k0 + seg);
    cpa16(base + SLAB + ro + 5120u,   Al + (size_t)(r0 + 64) * strideA + k0 + seg);
    cpa16(base + 2*SLAB + ro,         Bh + (size_t)r0 * strideB + k0 + seg);
    cpa16(base + 2*SLAB + ro + 5120u, Bh + (size_t)(r0 + 64) * strideB + k0 + seg);
    cpa16(base + 3*SLAB + ro,         Bl + (size_t)r0 * strideB + k0 + seg);
    cpa16(base + 3*SLAB + ro + 5120u, Bl + (size_t)(r0 + 64) * strideB + k0 + seg);
    asm volatile("cp.async.commit_group;");
}

// GEMM inner on one staged chunk: warp computes its 32x64 tile over k=32.
// TERM-MAJOR mma order within each j-block: chain distance on each accumulator
// grows from 1 to 4 mmas, covering HMMA latency. Same instructions, same math.
__device__ __forceinline__ void chunk_mma(uint32_t aHi, uint32_t bHi, int lane, int wm, int wn,
                                          float c[2][8][4]) {
    const uint32_t aAddr = aHi + (uint32_t)(wm * 32 + (lane & 15)) * 80u + ((lane >> 4) * 8u) * 2u;
    const uint32_t bAddr = bHi + (uint32_t)(wn * 64 + (lane & 7) + (((lane >> 4) & 1) * 8)) * 80u
                         + (((lane >> 3) & 1) * 8u) * 2u;
#pragma unroll
    for (int kh = 0; kh < 2; kh++) {
        const uint32_t ko = kh * 32u;
        unsigned ah[2][4], al[2][4];
        ldsm_x4(ah[0], aAddr + ko);
        ldsm_x4(ah[1], aAddr + 1280u + ko);
        ldsm_x4(al[0], aAddr + SLAB + ko);
        ldsm_x4(al[1], aAddr + SLAB + 1280u + ko);
#pragma unroll
        for (int j = 0; j < 4; j++) {
            unsigned bh4[4], bl4[4];
            ldsm_x4(bh4, bAddr + (uint32_t)j * 1280u + ko);
            ldsm_x4(bl4, bAddr + (uint32_t)j * 1280u + SLAB + ko);
            // term hi*hi: 4 mmas on 4 distinct accumulators
#pragma unroll
            for (int nn = 0; nn < 2; nn++) {
                unsigned b2[2] = {bh4[nn * 2], bh4[nn * 2 + 1]};
                mma16816(c[0][j * 2 + nn], ah[0], b2);
                mma16816(c[1][j * 2 + nn], ah[1], b2);
            }
            // term lo*hi
#pragma unroll
            for (int nn = 0; nn < 2; nn++) {
                unsigned b2[2] = {bh4[nn * 2], bh4[nn * 2 + 1]};
                mma16816(c[0][j * 2 + nn], al[0], b2);
                mma16816(c[1][j * 2 + nn], al[1], b2);
            }
            // term hi*lo
#pragma unroll
            for (int nn = 0; nn < 2; nn++) {
                unsigned b2[2] = {bl4[nn * 2], bl4[nn * 2 + 1]};
                mma16816(c[0][j * 2 + nn], ah[0], b2);
                mma16816(c[1][j * 2 + nn], ah[1], b2);
            }
        }
    }
}

// Pipelined tile GEMM over NC chunks of k=32. Two stages of dynamic smem.
__device__ __forceinline__ void tile_gemm(
    uint32_t sb, const ushort_t* Ah, const ushort_t* Al,
    const ushort_t* Bh, const ushort_t* Bl,
    size_t strideA, size_t strideB, int NC, int tid, float c[2][8][4]) {
    const int lane = tid & 31, wid = tid >> 5;
    const int wm = wid & 3, wn = wid >> 2;
    const int r0 = tid >> 2, seg = (tid & 3) * 8;

    stage_issue(sb, Ah, Al, Bh, Bl, strideA, strideB, 0, r0, seg);
    for (int kc = 0; kc < NC; kc++) {
        const int s = kc & 1;
        if (kc + 1 < NC) {
            stage_issue(sb + (uint32_t)(s ^ 1) * STAGE, Ah, Al, Bh, Bl,
                        strideA, strideB, (kc + 1) * 32, r0, seg);
            asm volatile("cp.async.wait_group 1;");
        } else {
            asm volatile("cp.async.wait_group 0;");
        }
        __syncthreads();
        const uint32_t base = sb + (uint32_t)s * STAGE;
        chunk_mma(base, base + 2*SLAB, lane, wm, wn, c);
        __syncthreads();
    }
}

// ---------------- kernel 0: zero -----------------------------------------------
__global__ void zero_kernel(float* __restrict__ out) {
    int i = blockIdx.x * blockDim.x + threadIdx.x;
    if (i < BATCH * SEQ * HEAD) out[i] = 0.0f;
    if (i < BATCH * SEQ) g_colsum[i] = 0.0f;
}

// ---------------- prep: split X ------------------------------------------------
__global__ __launch_bounds__(256) void prep_x(const float* __restrict__ X) {
    int p = blockIdx.x * 256 + threadIdx.x;
    int row = p >> 9, kp = (p & 511) * 2;
    float2 v = *(const float2*)(X + (size_t)row * EMB + kp);
    unsigned hh, ll;
    splitpack(v.x, v.y, hh, ll);
    *(unsigned*)&g_xh[(size_t)row * EMB + kp] = hh;
    *(unsigned*)&g_xl[(size_t)row * EMB + kp] = ll;
}

// ---------------- prep: split W^T ----------------------------------------------
__global__ __launch_bounds__(256) void prep_w(const float* __restrict__ Wq,
                                              const float* __restrict__ Wk,
                                              const float* __restrict__ Wv) {
    int p = blockIdx.x * 256 + threadIdx.x;
    int mat = p >> 16;
    int rem = p & 65535;
    int n = rem >> 9, kp = (rem & 511) * 2;
    const float* W = (mat == 0) ? Wq : (mat == 1) ? Wk : Wv;
    float v0 = W[(size_t)kp * HEAD + n];
    float v1 = W[(size_t)(kp + 1) * HEAD + n];
    unsigned hh, ll;
    splitpack(v0, v1, hh, ll);
    size_t off = (size_t)(mat * HEAD + n) * EMB + kp;
    *(unsigned*)&g_wth[off] = hh;
    *(unsigned*)&g_wtl[off] = ll;
}

// ---------------- kernel 1: QKV ------------------------------------------------
__global__ __launch_bounds__(256, 2) void qkv_tc(void) {
    extern __shared__ ushort_t dynS[];
    const int tid = threadIdx.x, lane = tid & 31, wid = tid >> 5;
    const int wm = wid & 3, wn = wid >> 2;
    const int rt = blockIdx.x, mat = blockIdx.y;
    const uint32_t sb = smem_u32(dynS);

    float c[2][8][4];
#pragma unroll
    for (int m = 0; m < 2; m++)
#pragma unroll
        for (int n = 0; n < 8; n++)
#pragma unroll
            for (int i = 0; i < 4; i++) c[m][n][i] = 0.0f;

    tile_gemm(sb,
              g_xh + (size_t)(rt * 128) * EMB, g_xl + (size_t)(rt * 128) * EMB,
              g_wth + (size_t)(mat * HEAD) * EMB, g_wtl + (size_t)(mat * HEAD) * EMB,
              EMB, EMB, 32, tid, c);

    const int gid = lane >> 2, tig = lane & 3;
    if (mat == 2) {
#pragma unroll
        for (int m = 0; m < 2; m++) {
            const int r = rt * 128 + wm * 32 + m * 16 + gid;
#pragma unroll
            for (int n = 0; n < 8; n++) {
                const int col = wn * 64 + n * 8 + tig * 2;
                *(float2*)(g_v + (size_t)r * HEAD + col)       = make_float2(c[m][n][0], c[m][n][1]);
                *(float2*)(g_v + (size_t)(r + 8) * HEAD + col) = make_float2(c[m][n][2], c[m][n][3]);
            }
        }
    } else {
        ushort_t* Yh = (mat == 0) ? g_qh : g_kh;
        ushort_t* Yl = (mat == 0) ? g_ql : g_kl;
        const float sc = (mat == 0) ? SCALE : 1.0f;
#pragma unroll
        for (int m = 0; m < 2; m++) {
            const int r = rt * 128 + wm * 32 + m * 16 + gid;
#pragma unroll
            for (int n = 0; n < 8; n++) {
                const int col = wn * 64 + n * 8 + tig * 2;
                unsigned hh, ll;
                splitpack(c[m][n][0] * sc, c[m][n][1] * sc, hh, ll);
                *(unsigned*)&Yh[(size_t)r * HEAD + col] = hh;
                *(unsigned*)&Yl[(size_t)r * HEAD + col] = ll;
                splitpack(c[m][n][2] * sc, c[m][n][3] * sc, hh, ll);
                *(unsigned*)&Yh[(size_t)(r + 8) * HEAD + col] = hh;
                *(unsigned*)&Yl[(size_t)(r + 8) * HEAD + col] = ll;
            }
        }
    }
}

// ---------------- kernel 2: scores ---------------------------------------------
__global__ __launch_bounds__(256, 2) void scores_tc(void) {
    extern __shared__ ushort_t dynS[];
    __shared__ float s_col[128];
    const int tid = threadIdx.x, lane = tid & 31, wid = tid >> 5;
    const int wm = wid & 3, wn = wid >> 2;
    const int b = blockIdx.x / NTRI;
    int qt, kt;
    tri_decode(blockIdx.x % NTRI, qt, kt);
    const uint32_t sb = smem_u32(dynS);

    if (tid < 128) s_col[tid] = 0.0f;

    float c[2][8][4];
#pragma unroll
    for (int m = 0; m < 2; m++)
#pragma unroll
        for (int n = 0; n < 8; n++)
#pragma unroll
            for (int i = 0; i < 4; i++) c[m][n][i] = 0.0f;

    tile_gemm(sb,
              g_qh + (size_t)(b * SEQ + qt * 128) * HEAD, g_ql + (size_t)(b * SEQ + qt * 128) * HEAD,
              g_kh + (size_t)(b * SEQ + kt * 128) * HEAD, g_kl + (size_t)(b * SEQ + kt * 128) * HEAD,
              HEAD, HEAD, 4, tid, c);

    const int gid = lane >> 2, tig = lane & 3;
    float p0[8], p1[8];
#pragma unroll
    for (int n = 0; n < 8; n++) { p0[n] = 0.0f; p1[n] = 0.0f; }

#pragma unroll
    for (int m = 0; m < 2; m++) {
        const int r   = wm * 32 + m * 16 + gid;
        const int gq0 = qt * 128 + r;
        const int gq1 = gq0 + 8;
#pragma unroll
        for (int n = 0; n < 8; n++) {
            const int cn = wn * 64 + n * 8 + tig * 2;
            const int gk = kt * 128 + cn;
            float e0 = (gq0 >= gk)     ? fast_exp(c[m][n][0]) : 0.0f;
            float e1 = (gq0 >= gk + 1) ? fast_exp(c[m][n][1]) : 0.0f;
            float e2 = (gq1 >= gk)     ? fast_exp(c[m][n][2]) : 0.0f;
            float e3 = (gq1 >= gk + 1) ? fast_exp(c[m][n][3]) : 0.0f;
            p0[n] += e0 + e2;
            p1[n] += e1 + e3;
            unsigned hh, ll;
            size_t base0 = ((size_t)b * SEQ + gq0) * SEQ + gk;
            splitpack(e0, e1, hh, ll);
            *(unsigned*)&g_eh[base0] = hh;
            *(unsigned*)&g_el[base0] = ll;
            size_t base1 = ((size_t)b * SEQ + gq1) * SEQ + gk;
            splitpack(e2, e3, hh, ll);
            *(unsigned*)&g_eh[base1] = hh;
            *(unsigned*)&g_el[base1] = ll;
        }
    }
#pragma unroll
    for (int n = 0; n < 8; n++) {
        p0[n] += __shfl_down_sync(0xffffffff, p0[n], 16);
        p0[n] += __shfl_down_sync(0xffffffff, p0[n], 8);
        p0[n] += __shfl_down_sync(0xffffffff, p0[n], 4);
        p1[n] += __shfl_down_sync(0xffffffff, p1[n], 16);
        p1[n] += __shfl_down_sync(0xffffffff, p1[n], 8);
        p1[n] += __shfl_down_sync(0xffffffff, p1[n], 4);
    }
    if (lane < 4) {
#pragma unroll
        for (int n = 0; n < 8; n++) {
            atomicAdd(&s_col[wn * 64 + n * 8 + lane * 2],     p0[n]);
            atomicAdd(&s_col[wn * 64 + n * 8 + lane * 2 + 1], p1[n]);
        }
    }
    __syncthreads();
    if (tid < 128) atomicAdd(&g_colsum[b * SEQ + kt * 128 + tid], s_col[tid]);
}

// ---------------- kernel 3: vprep — (v*inv)^T split ----------------------------
__global__ __launch_bounds__(256) void vprep_kernel() {
    __shared__ ushort_t sh[128][72], sl[128][72];
    const int tid   = threadIdx.x;
    const int batch = blockIdx.x >> 5;
    const int kt64  = blockIdx.x & 31;

    const int r  = tid >> 2;
    const int cb = (tid & 3) * 32;
    const int key = batch * SEQ + kt64 * 64 + r;
    const float inv = 1.0f / g_colsum[key];
    const float* vp = g_v + (size_t)key * HEAD + cb;
#pragma unroll
    for (int j = 0; j < 8; j++) {
        float4 v4 = *(const float4*)(vp + j * 4);
        float v[4] = {v4.x, v4.y, v4.z, v4.w};
#pragma unroll
        for (int i = 0; i < 4; i++) {
            ushort_t h, l;
            split2(v[i] * inv, h, l);
            sh[cb + j * 4 + i][r] = h;
            sl[cb + j * 4 + i][r] = l;
        }
    }
    __syncthreads();
    const int h  = tid >> 1;
    const int kc = (tid & 1) * 32;
    size_t gbase = (size_t)(batch * HEAD + h) * SEQ + kt64 * 64 + kc;
#pragma unroll
    for (int j = 0; j < 4; j++) {
        uint2 u0 = *(const uint2*)&sh[h][kc + j * 8];
        uint2 u1 = *(const uint2*)&sh[h][kc + j * 8 + 4];
        *(uint4*)&g_vth[gbase + j * 8] = make_uint4(u0.x, u0.y, u1.x, u1.y);
        uint2 w0 = *(const uint2*)&sl[h][kc + j * 8];
        uint2 w1 = *(const uint2*)&sl[h][kc + j * 8 + 4];
        *(uint4*)&g_vtl[gbase + j * 8] = make_uint4(w0.x, w0.y, w1.x, w1.y);
    }
}

// ---------------- kernel 4: out = expS' @ v' -----------------------------------
__global__ __launch_bounds__(256, 2) void out_tc(float* __restrict__ out) {
    extern __shared__ ushort_t dynS[];
    const int tid = threadIdx.x, lane = tid & 31, wid = tid >> 5;
    const int wm = wid & 3, wn = wid >> 2;
    const int b = blockIdx.x / NTRI;
    int qt, kt;
    tri_decode(blockIdx.x % NTRI, qt, kt);
    const uint32_t sb = smem_u32(dynS);

    float c[2][8][4];
#pragma unroll
    for (int m = 0; m < 2; m++)
#pragma unroll
        for (int n = 0; n < 8; n++)
#pragma unroll
            for (int i = 0; i < 4; i++) c[m][n][i] = 0.0f;

    tile_gemm(sb,
              g_eh + ((size_t)b * SEQ + qt * 128) * SEQ + kt * 128,
              g_el + ((size_t)b * SEQ + qt * 128) * SEQ + kt * 128,
              g_vth + (size_t)(b * HEAD) * SEQ + kt * 128,
              g_vtl + (size_t)(b * HEAD) * SEQ + kt * 128,
              SEQ, SEQ, 4, tid, c);

    const int gid = lane >> 2, tig = lane & 3;
#pragma unroll
    for (int m = 0; m < 2; m++) {
        const int r = qt * 128 + wm * 32 + m * 16 + gid;
#pragma unroll
        for (int n = 0; n < 8; n++) {
            const int cn = wn * 64 + n * 8 + tig * 2;
            float* op = out + ((size_t)b * SEQ + r) * HEAD + cn;
            atomicAdd(op,     c[m][n][0]);
            atomicAdd(op + 1, c[m][n][1]);
            atomicAdd(op + (size_t)8 * HEAD,     c[m][n][2]);
            atomicAdd(op + (size_t)8 * HEAD + 1, c[m][n][3]);
        }
    }
}

// ---------------- launch --------------------------------------------------------
extern "C" void kernel_launch(void* const* d_in, const int* in_sizes, int n_in,
                              void* d_out, int out_size) {
    const float* X  = (const float*)d_in[0];
    const float* Wq = (const float*)d_in[1];
    const float* Wk = (const float*)d_in[2];
    const float* Wv = (const float*)d_in[3];
    float* out = (float*)d_out;

    const int smem = 2 * 40960;
    cudaFuncSetAttribute(qkv_tc,    cudaFuncAttributeMaxDynamicSharedMemorySize, smem);
    cudaFuncSetAttribute(scores_tc, cudaFuncAttributeMaxDynamicSharedMemorySize, smem);
    cudaFuncSetAttribute(out_tc,    cudaFuncAttributeMaxDynamicSharedMemorySize, smem);

    zero_kernel<<<(BATCH * SEQ * HEAD + 255) / 256, 256>>>(out);
    prep_x<<<BATCH * SEQ * EMB / 2 / 256, 256>>>(X);
    prep_w<<<3 * HEAD * EMB / 2 / 256, 256>>>(Wq, Wk, Wv);
    qkv_tc<<<dim3(BATCH * SEQ / 128, 3), 256, smem>>>();
    scores_tc<<<BATCH * NTRI, 256, smem>>>();
    vprep_kernel<<<BATCH * SEQ / 64, 256>>>();
    out_tc<<<BATCH * NTRI, 256, smem>>>(out);
}

// round 14
// speedup vs baseline: 1.3875x; 1.2655x over previous
#include <cuda_runtime.h>
#include <cuda_fp16.h>
#include <math.h>
#include <stdint.h>

#define BATCH 8
#define SEQ   2048
#define EMB   1024
#define HEAD  128
#define NTRI  136            // lower-tri 128x128 tiles per batch
#define SCALE 0.03125f       // 1/sqrt(1024)

typedef unsigned short ushort_t;

// Stage geometry: 3 slabs (Ah, Al, Bh) of [128][40] ushort = 10240B each; stage = 30720B.
#define SLAB  10240u
#define STAGE 30720u

// ---------------- global scratch: fp16 split-A / single-B arrays ----------------
__device__ ushort_t g_xh[BATCH * SEQ * EMB], g_xl[BATCH * SEQ * EMB];     // X fp16 split [row][emb]
__device__ ushort_t g_wt[3 * HEAD * EMB];                                 // W^T fp16 [mat][head][emb]
__device__ ushort_t g_qh[BATCH * SEQ * HEAD], g_ql[BATCH * SEQ * HEAD];   // q' fp16 split [tok][head]
__device__ ushort_t g_kh[BATCH * SEQ * HEAD];                             // k fp16 [tok][head]
__device__ ushort_t g_vth[BATCH * HEAD * SEQ];                            // (v*inv)^T fp16 [head][key]
__device__ ushort_t g_eh[(size_t)BATCH * SEQ * SEQ];                      // expS hi fp16, 64MB
__device__ ushort_t g_el[(size_t)BATCH * SEQ * SEQ];                      // expS lo fp16, 64MB
__device__ float    g_v[BATCH * SEQ * HEAD];
__device__ float    g_colsum[BATCH * SEQ];

// ---------------- helpers ------------------------------------------------------
__device__ __forceinline__ uint32_t smem_u32(const void* p) {
    uint32_t a;
    asm("{ .reg .u64 t; cvta.to.shared.u64 t, %1; cvt.u32.u64 %0, t; }" : "=r"(a) : "l"(p));
    return a;
}
__device__ __forceinline__ void cpa16(uint32_t dst, const void* src) {
    asm volatile("cp.async.cg.shared.global [%0], [%1], 16;" :: "r"(dst), "l"(src));
}
__device__ __forceinline__ float fast_exp(float x) {
    float r = 2.0876757e-9f;
    r = fmaf(r, x, 2.5052108e-8f);
    r = fmaf(r, x, 2.7557319e-7f);
    r = fmaf(r, x, 2.7557319e-6f);
    r = fmaf(r, x, 2.4801587e-5f);
    r = fmaf(r, x, 1.9841270e-4f);
    r = fmaf(r, x, 1.3888889e-3f);
    r = fmaf(r, x, 8.3333333e-3f);
    r = fmaf(r, x, 4.1666667e-2f);
    r = fmaf(r, x, 1.6666667e-1f);
    r = fmaf(r, x, 0.5f);
    r = fmaf(r, x, 1.0f);
    r = fmaf(r, x, 1.0f);
    if (fabsf(x) > 2.0f) r = __expf(x);
    return r;
}
__device__ __forceinline__ void tri_decode(int t, int& qt, int& kt) {
    int q = (int)((sqrtf(8.0f * (float)t + 1.0f) - 1.0f) * 0.5f);
    while ((q + 1) * (q + 2) / 2 <= t) q++;
    while (q * (q + 1) / 2 > t) q--;
    qt = q;
    kt = t - q * (q + 1) / 2;
}
// fp16 hi/lo split: x = h + l with |residual| <= 2^-22 |x|
__device__ __forceinline__ void split2h(float x, ushort_t& h, ushort_t& l) {
    __half hh = __float2half_rn(x);
    float r = x - __half2float(hh);
    __half hl = __float2half_rn(r);
    h = *(ushort_t*)&hh;
    l = *(ushort_t*)&hl;
}
__device__ __forceinline__ void splitpackh(float x0, float x1, unsigned& hh, unsigned& ll) {
    ushort_t h0, l0, h1, l1;
    split2h(x0, h0, l0);
    split2h(x1, h1, l1);
    hh = (unsigned)h0 | ((unsigned)h1 << 16);
    ll = (unsigned)l0 | ((unsigned)l1 << 16);
}
__device__ __forceinline__ unsigned pack_h2(float a, float b) {
    __half2 h = __floats2half2_rn(a, b);
    return *(unsigned*)&h;
}
__device__ __forceinline__ void mma16816(float c[4], const unsigned a[4], const unsigned b[2]) {
    asm volatile(
        "mma.sync.aligned.m16n8k16.row.col.f32.f16.f16.f32 "
        "{%0,%1,%2,%3}, {%4,%5,%6,%7}, {%8,%9}, {%0,%1,%2,%3};\n"
        : "+f"(c[0]), "+f"(c[1]), "+f"(c[2]), "+f"(c[3])
        : "r"(a[0]), "r"(a[1]), "r"(a[2]), "r"(a[3]), "r"(b[0]), "r"(b[1]));
}
__device__ __forceinline__ void ldsm_x4(unsigned* r, uint32_t a) {
    asm volatile("ldmatrix.sync.aligned.m8n8.x4.shared.b16 {%0,%1,%2,%3}, [%4];"
                 : "=r"(r[0]), "=r"(r[1]), "=r"(r[2]), "=r"(r[3]) : "r"(a));
}

// Issue one stage's cp.async loads: 3 slabs (Ah, Al, Bh), 2 rows x 16B per thread per slab.
__device__ __forceinline__ void stage_issue(
    uint32_t base, const ushort_t* Ah, const ushort_t* Al, const ushort_t* Bh,
    size_t strideA, size_t strideB, int k0, int r0, int seg) {
    const uint32_t ro = (uint32_t)r0 * 80u + (uint32_t)seg * 2u;
    cpa16(base + ro,                  Ah + (size_t)r0 * strideA + k0 + seg);
    cpa16(base + ro + 5120u,          Ah + (size_t)(r0 + 64) * strideA + k0 + seg);
    cpa16(base + SLAB + ro,           Al + (size_t)r0 * strideA + k0 + seg);
    cpa16(base + SLAB + ro + 5120u,   Al + (size_t)(r0 + 64) * strideA + k0 + seg);
    cpa16(base + 2*SLAB + ro,         Bh + (size_t)r0 * strideB + k0 + seg);
    cpa16(base + 2*SLAB + ro + 5120u, Bh + (size_t)(r0 + 64) * strideB + k0 + seg);
    asm volatile("cp.async.commit_group;");
}

// GEMM inner on one staged chunk (k=32): 2-term fp16 split — c += Ah*B + Al*B.
// Term-major within each j-block (4 independent accumulator chains).
__device__ __forceinline__ void chunk_mma(uint32_t base, int lane, int wm, int wn,
                                          float c[2][8][4]) {
    const uint32_t aAddr = base + (uint32_t)(wm * 32 + (lane & 15)) * 80u + ((lane >> 4) * 8u) * 2u;
    const uint32_t bAddr = base + 2*SLAB
                         + (uint32_t)(wn * 64 + (lane & 7) + (((lane >> 4) & 1) * 8)) * 80u
                         + (((lane >> 3) & 1) * 8u) * 2u;
#pragma unroll
    for (int kh = 0; kh < 2; kh++) {
        const uint32_t ko = kh * 32u;
        unsigned ah[2][4], al[2][4];
        ldsm_x4(ah[0], aAddr + ko);
        ldsm_x4(ah[1], aAddr + 1280u + ko);
        ldsm_x4(al[0], aAddr + SLAB + ko);
        ldsm_x4(al[1], aAddr + SLAB + 1280u + ko);
#pragma unroll
        for (int j = 0; j < 4; j++) {
            unsigned bh4[4];
            ldsm_x4(bh4, bAddr + (uint32_t)j * 1280u + ko);
            // term hi: 4 mmas on 4 distinct accumulators
#pragma unroll
            for (int nn = 0; nn < 2; nn++) {
                unsigned b2[2] = {bh4[nn * 2], bh4[nn * 2 + 1]};
                mma16816(c[0][j * 2 + nn], ah[0], b2);
                mma16816(c[1][j * 2 + nn], ah[1], b2);
            }
            // term lo
#pragma unroll
            for (int nn = 0; nn < 2; nn++) {
                unsigned b2[2] = {bh4[nn * 2], bh4[nn * 2 + 1]};
                mma16816(c[0][j * 2 + nn], al[0], b2);
                mma16816(c[1][j * 2 + nn], al[1], b2);
            }
        }
    }
}

// Pipelined tile GEMM over NC chunks of k=32. Two stages of dynamic smem.
__device__ __forceinline__ void tile_gemm(
    uint32_t sb, const ushort_t* Ah, const ushort_t* Al, const ushort_t* Bh,
    size_t strideA, size_t strideB, int NC, int tid, float c[2][8][4]) {
    const int lane = tid & 31, wid = tid >> 5;
    const int wm = wid & 3, wn = wid >> 2;
    const int r0 = tid >> 2, seg = (tid & 3) * 8;

    stage_issue(sb, Ah, Al, Bh, strideA, strideB, 0, r0, seg);
    for (int kc = 0; kc < NC; kc++) {
        const int s = kc & 1;
        if (kc + 1 < NC) {
            stage_issue(sb + (uint32_t)(s ^ 1) * STAGE, Ah, Al, Bh,
                        strideA, strideB, (kc + 1) * 32, r0, seg);
            asm volatile("cp.async.wait_group 1;");
        } else {
            asm volatile("cp.async.wait_group 0;");
        }
        __syncthreads();
        chunk_mma(sb + (uint32_t)s * STAGE, lane, wm, wn, c);
        __syncthreads();
    }
}

// ---------------- kernel 0: zero -----------------------------------------------
__global__ void zero_kernel(float* __restrict__ out) {
    int i = blockIdx.x * blockDim.x + threadIdx.x;
    if (i < BATCH * SEQ * HEAD) out[i] = 0.0f;
    if (i < BATCH * SEQ) g_colsum[i] = 0.0f;
}

// ---------------- prep: split X (fp16 hi/lo) ------------------------------------
__global__ __launch_bounds__(256) void prep_x(const float* __restrict__ X) {
    int p = blockIdx.x * 256 + threadIdx.x;
    int row = p >> 9, kp = (p & 511) * 2;
    float2 v = *(const float2*)(X + (size_t)row * EMB + kp);
    unsigned hh, ll;
    splitpackh(v.x, v.y, hh, ll);
    *(unsigned*)&g_xh[(size_t)row * EMB + kp] = hh;
    *(unsigned*)&g_xl[(size_t)row * EMB + kp] = ll;
}

// ---------------- prep: W^T single fp16 -----------------------------------------
__global__ __launch_bounds__(256) void prep_w(const float* __restrict__ Wq,
                                              const float* __restrict__ Wk,
                                              const float* __restrict__ Wv) {
    int p = blockIdx.x * 256 + threadIdx.x;
    int mat = p >> 16;
    int rem = p & 65535;
    int n = rem >> 9, kp = (rem & 511) * 2;
    const float* W = (mat == 0) ? Wq : (mat == 1) ? Wk : Wv;
    float v0 = W[(size_t)kp * HEAD + n];
    float v1 = W[(size_t)(kp + 1) * HEAD + n];
    *(unsigned*)&g_wt[(size_t)(mat * HEAD + n) * EMB + kp] = pack_h2(v0, v1);
}

// ---------------- kernel 1: QKV ------------------------------------------------
__global__ __launch_bounds__(256, 2) void qkv_tc(void) {
    extern __shared__ ushort_t dynS[];
    const int tid = threadIdx.x, lane = tid & 31, wid = tid >> 5;
    const int wm = wid & 3, wn = wid >> 2;
    const int rt = blockIdx.x, mat = blockIdx.y;
    const uint32_t sb = smem_u32(dynS);

    float c[2][8][4];
#pragma unroll
    for (int m = 0; m < 2; m++)
#pragma unroll
        for (int n = 0; n < 8; n++)
#pragma unroll
            for (int i = 0; i < 4; i++) c[m][n][i] = 0.0f;

    tile_gemm(sb,
              g_xh + (size_t)(rt * 128) * EMB, g_xl + (size_t)(rt * 128) * EMB,
              g_wt + (size_t)(mat * HEAD) * EMB,
              EMB, EMB, 32, tid, c);

    const int gid = lane >> 2, tig = lane & 3;
    if (mat == 2) {
#pragma unroll
        for (int m = 0; m < 2; m++) {
            const int r = rt * 128 + wm * 32 + m * 16 + gid;
#pragma unroll
            for (int n = 0; n < 8; n++) {
                const int col = wn * 64 + n * 8 + tig * 2;
                *(float2*)(g_v + (size_t)r * HEAD + col)       = make_float2(c[m][n][0], c[m][n][1]);
                *(float2*)(g_v + (size_t)(r + 8) * HEAD + col) = make_float2(c[m][n][2], c[m][n][3]);
            }
        }
    } else if (mat == 0) {
        // q' = q * SCALE, fp16 split (A operand of scores)
#pragma unroll
        for (int m = 0; m < 2; m++) {
            const int r = rt * 128 + wm * 32 + m * 16 + gid;
#pragma unroll
            for (int n = 0; n < 8; n++) {
                const int col = wn * 64 + n * 8 + tig * 2;
                unsigned hh, ll;
                splitpackh(c[m][n][0] * SCALE, c[m][n][1] * SCALE, hh, ll);
                *(unsigned*)&g_qh[(size_t)r * HEAD + col] = hh;
                *(unsigned*)&g_ql[(size_t)r * HEAD + col] = ll;
                splitpackh(c[m][n][2] * SCALE, c[m][n][3] * SCALE, hh, ll);
                *(unsigned*)&g_qh[(size_t)(r + 8) * HEAD + col] = hh;
                *(unsigned*)&g_ql[(size_t)(r + 8) * HEAD + col] = ll;
            }
        }
    } else {
        // k single fp16 (B operand of scores)
#pragma unroll
        for (int m = 0; m < 2; m++) {
            const int r = rt * 128 + wm * 32 + m * 16 + gid;
#pragma unroll
            for (int n = 0; n < 8; n++) {
                const int col = wn * 64 + n * 8 + tig * 2;
                *(unsigned*)&g_kh[(size_t)r * HEAD + col]       = pack_h2(c[m][n][0], c[m][n][1]);
                *(unsigned*)&g_kh[(size_t)(r + 8) * HEAD + col] = pack_h2(c[m][n][2], c[m][n][3]);
            }
        }
    }
}

// ---------------- kernel 2: scores ---------------------------------------------
__global__ __launch_bounds__(256, 2) void scores_tc(void) {
    extern __shared__ ushort_t dynS[];
    __shared__ float s_col[128];
    const int tid = threadIdx.x, lane = tid & 31, wid = tid >> 5;
    const int wm = wid & 3, wn = wid >> 2;
    const int b = blockIdx.x / NTRI;
    int qt, kt;
    tri_decode(blockIdx.x % NTRI, qt, kt);
    const uint32_t sb = smem_u32(dynS);

    if (tid < 128) s_col[tid] = 0.0f;

    float c[2][8][4];
#pragma unroll
    for (int m = 0; m < 2; m++)
#pragma unroll
        for (int n = 0; n < 8; n++)
#pragma unroll
            for (int i = 0; i < 4; i++) c[m][n][i] = 0.0f;

    tile_gemm(sb,
              g_qh + (size_t)(b * SEQ + qt * 128) * HEAD, g_ql + (size_t)(b * SEQ + qt * 128) * HEAD,
              g_kh + (size_t)(b * SEQ + kt * 128) * HEAD,
              HEAD, HEAD, 4, tid, c);

    const int gid = lane >> 2, tig = lane & 3;
    float p0[8], p1[8];
#pragma unroll
    for (int n = 0; n < 8; n++) { p0[n] = 0.0f; p1[n] = 0.0f; }

#pragma unroll
    for (int m = 0; m < 2; m++) {
        const int r   = wm * 32 + m * 16 + gid;
        const int gq0 = qt * 128 + r;
        const int gq1 = gq0 + 8;
#pragma unroll
        for (int n = 0; n < 8; n++) {
            const int cn = wn * 64 + n * 8 + tig * 2;
            const int gk = kt * 128 + cn;
            float e0 = (gq0 >= gk)     ? fast_exp(c[m][n][0]) : 0.0f;
            float e1 = (gq0 >= gk + 1) ? fast_exp(c[m][n][1]) : 0.0f;
            float e2 = (gq1 >= gk)     ? fast_exp(c[m][n][2]) : 0.0f;
            float e3 = (gq1 >= gk + 1) ? fast_exp(c[m][n][3]) : 0.0f;
            p0[n] += e0 + e2;
            p1[n] += e1 + e3;
            unsigned hh, ll;
            size_t base0 = ((size_t)b * SEQ + gq0) * SEQ + gk;
            splitpackh(e0, e1, hh, ll);
            *(unsigned*)&g_eh[base0] = hh;
            *(unsigned*)&g_el[base0] = ll;
            size_t base1 = ((size_t)b * SEQ + gq1) * SEQ + gk;
            splitpackh(e2, e3, hh, ll);
            *(unsigned*)&g_eh[base1] = hh;
            *(unsigned*)&g_el[base1] = ll;
        }
    }
#pragma unroll
    for (int n = 0; n < 8; n++) {
        p0[n] += __shfl_down_sync(0xffffffff, p0[n], 16);
        p0[n] += __shfl_down_sync(0xffffffff, p0[n], 8);
        p0[n] += __shfl_down_sync(0xffffffff, p0[n], 4);
        p1[n] += __shfl_down_sync(0xffffffff, p1[n], 16);
        p1[n] += __shfl_down_sync(0xffffffff, p1[n], 8);
        p1[n] += __shfl_down_sync(0xffffffff, p1[n], 4);
    }
    if (lane < 4) {
#pragma unroll
        for (int n = 0; n < 8; n++) {
            atomicAdd(&s_col[wn * 64 + n * 8 + lane * 2],     p0[n]);
            atomicAdd(&s_col[wn * 64 + n * 8 + lane * 2 + 1], p1[n]);
        }
    }
    __syncthreads();
    if (tid < 128) atomicAdd(&g_colsum[b * SEQ + kt * 128 + tid], s_col[tid]);
}

// ---------------- kernel 3: vprep — (v*inv)^T fp16 -----------------------------
__global__ __launch_bounds__(256) void vprep_kernel() {
    __shared__ ushort_t sh[128][72];
    const int tid   = threadIdx.x;
    const int batch = blockIdx.x >> 5;
    const int kt64  = blockIdx.x & 31;

    const int r  = tid >> 2;
    const int cb = (tid & 3) * 32;
    const int key = batch * SEQ + kt64 * 64 + r;
    const float inv = 1.0f / g_colsum[key];
    const float* vp = g_v + (size_t)key * HEAD + cb;
#pragma unroll
    for (int j = 0; j < 8; j++) {
        float4 v4 = *(const float4*)(vp + j * 4);
        float v[4] = {v4.x, v4.y, v4.z, v4.w};
#pragma unroll
        for (int i = 0; i < 4; i++) {
            __half h = __float2half_rn(v[i] * inv);
            sh[cb + j * 4 + i][r] = *(ushort_t*)&h;
        }
    }
    __syncthreads();
    const int h  = tid >> 1;
    const int kc = (tid & 1) * 32;
    size_t gbase = (size_t)(batch * HEAD + h) * SEQ + kt64 * 64 + kc;
#pragma unroll
    for (int j = 0; j < 4; j++) {
        uint2 u0 = *(const uint2*)&sh[h][kc + j * 8];
        uint2 u1 = *(const uint2*)&sh[h][kc + j * 8 + 4];
        *(uint4*)&g_vth[gbase + j * 8] = make_uint4(u0.x, u0.y, u1.x, u1.y);
    }
}

// ---------------- kernel 4: out = expS' @ v' -----------------------------------
__global__ __launch_bounds__(256, 2) void out_tc(float* __restrict__ out) {
    extern __shared__ ushort_t dynS[];
    const int tid = threadIdx.x, lane = tid & 31, wid = tid >> 5;
    const int wm = wid & 3, wn = wid >> 2;
    const int b = blockIdx.x / NTRI;
    int qt, kt;
    tri_decode(blockIdx.x % NTRI, qt, kt);
    const uint32_t sb = smem_u32(dynS);

    float c[2][8][4];
#pragma unroll
    for (int m = 0; m < 2; m++)
#pragma unroll
        for (int n = 0; n < 8; n++)
#pragma unroll
            for (int i = 0; i < 4; i++) c[m][n][i] = 0.0f;

    tile_gemm(sb,
              g_eh + ((size_t)b * SEQ + qt * 128) * SEQ + kt * 128,
              g_el + ((size_t)b * SEQ + qt * 128) * SEQ + kt * 128,
              g_vth + (size_t)(b * HEAD) * SEQ + kt * 128,
              SEQ, SEQ, 4, tid, c);

    const int gid = lane >> 2, tig = lane & 3;
#pragma unroll
    for (int m = 0; m < 2; m++) {
        const int r = qt * 128 + wm * 32 + m * 16 + gid;
#pragma unroll
        for (int n = 0; n < 8; n++) {
            const int cn = wn * 64 + n * 8 + tig * 2;
            float* op = out + ((size_t)b * SEQ + r) * HEAD + cn;
            atomicAdd(op,     c[m][n][0]);
            atomicAdd(op + 1, c[m][n][1]);
            atomicAdd(op + (size_t)8 * HEAD,     c[m][n][2]);
            atomicAdd(op + (size_t)8 * HEAD + 1, c[m][n][3]);
        }
    }
}

// ---------------- launch --------------------------------------------------------
extern "C" void kernel_launch(void* const* d_in, const int* in_sizes, int n_in,
                              void* d_out, int out_size) {
    const float* X  = (const float*)d_in[0];
    const float* Wq = (const float*)d_in[1];
    const float* Wk = (const float*)d_in[2];
    const float* Wv = (const float*)d_in[3];
    float* out = (float*)d_out;

    const int smem = 2 * STAGE;   // 61440
    cudaFuncSetAttribute(qkv_tc,    cudaFuncAttributeMaxDynamicSharedMemorySize, smem);
    cudaFuncSetAttribute(scores_tc, cudaFuncAttributeMaxDynamicSharedMemorySize, smem);
    cudaFuncSetAttribute(out_tc,    cudaFuncAttributeMaxDynamicSharedMemorySize, smem);

    zero_kernel<<<(BATCH * SEQ * HEAD + 255) / 256, 256>>>(out);
    prep_x<<<BATCH * SEQ * EMB / 2 / 256, 256>>>(X);
    prep_w<<<3 * HEAD * EMB / 2 / 256, 256>>>(Wq, Wk, Wv);
    qkv_tc<<<dim3(BATCH * SEQ / 128, 3), 256, smem>>>();
    scores_tc<<<BATCH * NTRI, 256, smem>>>();
    vprep_kernel<<<BATCH * SEQ / 64, 256>>>();
    out_tc<<<BATCH * NTRI, 256, smem>>>(out);
}

// round 15
// speedup vs baseline: 1.5371x; 1.1078x over previous
#include <cuda_runtime.h>
#include <cuda_fp16.h>
#include <math.h>
#include <stdint.h>

#define BATCH 8
#define SEQ   2048
#define EMB   1024
#define HEAD  128
#define NTRI  136            // lower-tri 128x128 tiles per batch
#define SCALE 0.03125f       // 1/sqrt(1024)

typedef unsigned short ushort_t;

// Slab = [128][40] ushort = 10240B. qkv stage = 3 slabs (Ah, Al, B) = 30720B.
// scores/out stage = 2 slabs (A, B) = 20480B.
#define SLAB    10240u
#define STAGE3  30720u
#define STAGE2  20480u

// ---------------- global scratch (fp16) -----------------------------------------
__device__ ushort_t g_xh[BATCH * SEQ * EMB], g_xl[BATCH * SEQ * EMB];   // X fp16 split [row][emb]
__device__ ushort_t g_wt[3 * HEAD * EMB];                               // W^T fp16 [mat][head][emb]
__device__ ushort_t g_qh[BATCH * SEQ * HEAD];                           // q' fp16 [tok][head]
__device__ ushort_t g_kh[BATCH * SEQ * HEAD];                           // k fp16 [tok][head]
__device__ ushort_t g_vth[BATCH * HEAD * SEQ];                          // (v*inv)^T fp16 [head][key]
__device__ ushort_t g_eh[(size_t)BATCH * SEQ * SEQ];                    // expS fp16, 64MB
__device__ float    g_v[BATCH * SEQ * HEAD];
__device__ float    g_colsum[BATCH * SEQ];

// ---------------- helpers ------------------------------------------------------
__device__ __forceinline__ uint32_t smem_u32(const void* p) {
    uint32_t a;
    asm("{ .reg .u64 t; cvta.to.shared.u64 t, %1; cvt.u32.u64 %0, t; }" : "=r"(a) : "l"(p));
    return a;
}
__device__ __forceinline__ void cpa16(uint32_t dst, const void* src) {
    asm volatile("cp.async.cg.shared.global [%0], [%1], 16;" :: "r"(dst), "l"(src));
}
__device__ __forceinline__ float fast_exp(float x) {
    float r = 2.0876757e-9f;
    r = fmaf(r, x, 2.5052108e-8f);
    r = fmaf(r, x, 2.7557319e-7f);
    r = fmaf(r, x, 2.7557319e-6f);
    r = fmaf(r, x, 2.4801587e-5f);
    r = fmaf(r, x, 1.9841270e-4f);
    r = fmaf(r, x, 1.3888889e-3f);
    r = fmaf(r, x, 8.3333333e-3f);
    r = fmaf(r, x, 4.1666667e-2f);
    r = fmaf(r, x, 1.6666667e-1f);
    r = fmaf(r, x, 0.5f);
    r = fmaf(r, x, 1.0f);
    r = fmaf(r, x, 1.0f);
    if (fabsf(x) > 2.0f) r = __expf(x);
    return r;
}
__device__ __forceinline__ void tri_decode(int t, int& qt, int& kt) {
    int q = (int)((sqrtf(8.0f * (float)t + 1.0f) - 1.0f) * 0.5f);
    while ((q + 1) * (q + 2) / 2 <= t) q++;
    while (q * (q + 1) / 2 > t) q--;
    qt = q;
    kt = t - q * (q + 1) / 2;
}
__device__ __forceinline__ void split2h(float x, ushort_t& h, ushort_t& l) {
    __half hh = __float2half_rn(x);
    float r = x - __half2float(hh);
    __half hl = __float2half_rn(r);
    h = *(ushort_t*)&hh;
    l = *(ushort_t*)&hl;
}
__device__ __forceinline__ void splitpackh(float x0, float x1, unsigned& hh, unsigned& ll) {
    ushort_t h0, l0, h1, l1;
    split2h(x0, h0, l0);
    split2h(x1, h1, l1);
    hh = (unsigned)h0 | ((unsigned)h1 << 16);
    ll = (unsigned)l0 | ((unsigned)l1 << 16);
}
__device__ __forceinline__ unsigned pack_h2(float a, float b) {
    __half2 h = __floats2half2_rn(a, b);
    return *(unsigned*)&h;
}
__device__ __forceinline__ void mma16816(float c[4], const unsigned a[4], const unsigned b[2]) {
    asm volatile(
        "mma.sync.aligned.m16n8k16.row.col.f32.f16.f16.f32 "
        "{%0,%1,%2,%3}, {%4,%5,%6,%7}, {%8,%9}, {%0,%1,%2,%3};\n"
        : "+f"(c[0]), "+f"(c[1]), "+f"(c[2]), "+f"(c[3])
        : "r"(a[0]), "r"(a[1]), "r"(a[2]), "r"(a[3]), "r"(b[0]), "r"(b[1]));
}
__device__ __forceinline__ void ldsm_x4(unsigned* r, uint32_t a) {
    asm volatile("ldmatrix.sync.aligned.m8n8.x4.shared.b16 {%0,%1,%2,%3}, [%4];"
                 : "=r"(r[0]), "=r"(r[1]), "=r"(r[2]), "=r"(r[3]) : "r"(a));
}

// ---------------- 2-term path (qkv): slabs Ah, Al, B ----------------------------
__device__ __forceinline__ void stage_issue3(
    uint32_t base, const ushort_t* Ah, const ushort_t* Al, const ushort_t* Bh,
    size_t strideA, size_t strideB, int k0, int r0, int seg) {
    const uint32_t ro = (uint32_t)r0 * 80u + (uint32_t)seg * 2u;
    cpa16(base + ro,                  Ah + (size_t)r0 * strideA + k0 + seg);
    cpa16(base + ro + 5120u,          Ah + (size_t)(r0 + 64) * strideA + k0 + seg);
    cpa16(base + SLAB + ro,           Al + (size_t)r0 * strideA + k0 + seg);
    cpa16(base + SLAB + ro + 5120u,   Al + (size_t)(r0 + 64) * strideA + k0 + seg);
    cpa16(base + 2*SLAB + ro,         Bh + (size_t)r0 * strideB + k0 + seg);
    cpa16(base + 2*SLAB + ro + 5120u, Bh + (size_t)(r0 + 64) * strideB + k0 + seg);
    asm volatile("cp.async.commit_group;");
}

__device__ __forceinline__ void chunk_mma3(uint32_t base, int lane, int wm, int wn,
                                           float c[2][8][4]) {
    const uint32_t aAddr = base + (uint32_t)(wm * 32 + (lane & 15)) * 80u + ((lane >> 4) * 8u) * 2u;
    const uint32_t bAddr = base + 2*SLAB
                         + (uint32_t)(wn * 64 + (lane & 7) + (((lane >> 4) & 1) * 8)) * 80u
                         + (((lane >> 3) & 1) * 8u) * 2u;
#pragma unroll
    for (int kh = 0; kh < 2; kh++) {
        const uint32_t ko = kh * 32u;
        unsigned ah[2][4], al[2][4];
        ldsm_x4(ah[0], aAddr + ko);
        ldsm_x4(ah[1], aAddr + 1280u + ko);
        ldsm_x4(al[0], aAddr + SLAB + ko);
        ldsm_x4(al[1], aAddr + SLAB + 1280u + ko);
#pragma unroll
        for (int j = 0; j < 4; j++) {
            unsigned bh4[4];
            ldsm_x4(bh4, bAddr + (uint32_t)j * 1280u + ko);
#pragma unroll
            for (int nn = 0; nn < 2; nn++) {
                unsigned b2[2] = {bh4[nn * 2], bh4[nn * 2 + 1]};
                mma16816(c[0][j * 2 + nn], ah[0], b2);
                mma16816(c[1][j * 2 + nn], ah[1], b2);
            }
#pragma unroll
            for (int nn = 0; nn < 2; nn++) {
                unsigned b2[2] = {bh4[nn * 2], bh4[nn * 2 + 1]};
                mma16816(c[0][j * 2 + nn], al[0], b2);
                mma16816(c[1][j * 2 + nn], al[1], b2);
            }
        }
    }
}

__device__ __forceinline__ void tile_gemm3(
    uint32_t sb, const ushort_t* Ah, const ushort_t* Al, const ushort_t* Bh,
    size_t strideA, size_t strideB, int NC, int tid, float c[2][8][4]) {
    const int lane = tid & 31, wid = tid >> 5;
    const int wm = wid & 3, wn = wid >> 2;
    const int r0 = tid >> 2, seg = (tid & 3) * 8;

    stage_issue3(sb, Ah, Al, Bh, strideA, strideB, 0, r0, seg);
    for (int kc = 0; kc < NC; kc++) {
        const int s = kc & 1;
        if (kc + 1 < NC) {
            stage_issue3(sb + (uint32_t)(s ^ 1) * STAGE3, Ah, Al, Bh,
                         strideA, strideB, (kc + 1) * 32, r0, seg);
            asm volatile("cp.async.wait_group 1;");
        } else {
            asm volatile("cp.async.wait_group 0;");
        }
        __syncthreads();
        chunk_mma3(sb + (uint32_t)s * STAGE3, lane, wm, wn, c);
        __syncthreads();
    }
}

// ---------------- 1-term path (scores, out): slabs A, B -------------------------
__device__ __forceinline__ void stage_issue2(
    uint32_t base, const ushort_t* A, const ushort_t* Bh,
    size_t strideA, size_t strideB, int k0, int r0, int seg) {
    const uint32_t ro = (uint32_t)r0 * 80u + (uint32_t)seg * 2u;
    cpa16(base + ro,                A + (size_t)r0 * strideA + k0 + seg);
    cpa16(base + ro + 5120u,        A + (size_t)(r0 + 64) * strideA + k0 + seg);
    cpa16(base + SLAB + ro,         Bh + (size_t)r0 * strideB + k0 + seg);
    cpa16(base + SLAB + ro + 5120u, Bh + (size_t)(r0 + 64) * strideB + k0 + seg);
    asm volatile("cp.async.commit_group;");
}

__device__ __forceinline__ void chunk_mma2(uint32_t base, int lane, int wm, int wn,
                                           float c[2][8][4]) {
    const uint32_t aAddr = base + (uint32_t)(wm * 32 + (lane & 15)) * 80u + ((lane >> 4) * 8u) * 2u;
    const uint32_t bAddr = base + SLAB
                         + (uint32_t)(wn * 64 + (lane & 7) + (((lane >> 4) & 1) * 8)) * 80u
                         + (((lane >> 3) & 1) * 8u) * 2u;
#pragma unroll
    for (int kh = 0; kh < 2; kh++) {
        const uint32_t ko = kh * 32u;
        unsigned ah[2][4];
        ldsm_x4(ah[0], aAddr + ko);
        ldsm_x4(ah[1], aAddr + 1280u + ko);
#pragma unroll
        for (int j = 0; j < 4; j++) {
            unsigned bh4[4];
            ldsm_x4(bh4, bAddr + (uint32_t)j * 1280u + ko);
#pragma unroll
            for (int nn = 0; nn < 2; nn++) {
                unsigned b2[2] = {bh4[nn * 2], bh4[nn * 2 + 1]};
                mma16816(c[0][j * 2 + nn], ah[0], b2);
                mma16816(c[1][j * 2 + nn], ah[1], b2);
            }
        }
    }
}

__device__ __forceinline__ void tile_gemm2(
    uint32_t sb, const ushort_t* A, const ushort_t* Bh,
    size_t strideA, size_t strideB, int NC, int tid, float c[2][8][4]) {
    const int lane = tid & 31, wid = tid >> 5;
    const int wm = wid & 3, wn = wid >> 2;
    const int r0 = tid >> 2, seg = (tid & 3) * 8;

    stage_issue2(sb, A, Bh, strideA, strideB, 0, r0, seg);
    for (int kc = 0; kc < NC; kc++) {
        const int s = kc & 1;
        if (kc + 1 < NC) {
            stage_issue2(sb + (uint32_t)(s ^ 1) * STAGE2, A, Bh,
                         strideA, strideB, (kc + 1) * 32, r0, seg);
            asm volatile("cp.async.wait_group 1;");
        } else {
            asm volatile("cp.async.wait_group 0;");
        }
        __syncthreads();
        chunk_mma2(sb + (uint32_t)s * STAGE2, lane, wm, wn, c);
        __syncthreads();
    }
}

// ---------------- kernel 0: zero -----------------------------------------------
__global__ void zero_kernel(float* __restrict__ out) {
    int i = blockIdx.x * blockDim.x + threadIdx.x;
    if (i < BATCH * SEQ * HEAD) out[i] = 0.0f;
    if (i < BATCH * SEQ) g_colsum[i] = 0.0f;
}

// ---------------- prep: split X (fp16 hi/lo) ------------------------------------
__global__ __launch_bounds__(256) void prep_x(const float* __restrict__ X) {
    int p = blockIdx.x * 256 + threadIdx.x;
    int row = p >> 9, kp = (p & 511) * 2;
    float2 v = *(const float2*)(X + (size_t)row * EMB + kp);
    unsigned hh, ll;
    splitpackh(v.x, v.y, hh, ll);
    *(unsigned*)&g_xh[(size_t)row * EMB + kp] = hh;
    *(unsigned*)&g_xl[(size_t)row * EMB + kp] = ll;
}

// ---------------- prep: W^T single fp16 -----------------------------------------
__global__ __launch_bounds__(256) void prep_w(const float* __restrict__ Wq,
                                              const float* __restrict__ Wk,
                                              const float* __restrict__ Wv) {
    int p = blockIdx.x * 256 + threadIdx.x;
    int mat = p >> 16;
    int rem = p & 65535;
    int n = rem >> 9, kp = (rem & 511) * 2;
    const float* W = (mat == 0) ? Wq : (mat == 1) ? Wk : Wv;
    float v0 = W[(size_t)kp * HEAD + n];
    float v1 = W[(size_t)(kp + 1) * HEAD + n];
    *(unsigned*)&g_wt[(size_t)(mat * HEAD + n) * EMB + kp] = pack_h2(v0, v1);
}

// ---------------- kernel 1: QKV (2-term split on X) -----------------------------
__global__ __launch_bounds__(256, 2) void qkv_tc(void) {
    extern __shared__ ushort_t dynS[];
    const int tid = threadIdx.x, lane = tid & 31, wid = tid >> 5;
    const int wm = wid & 3, wn = wid >> 2;
    const int rt = blockIdx.x, mat = blockIdx.y;
    const uint32_t sb = smem_u32(dynS);

    float c[2][8][4];
#pragma unroll
    for (int m = 0; m < 2; m++)
#pragma unroll
        for (int n = 0; n < 8; n++)
#pragma unroll
            for (int i = 0; i < 4; i++) c[m][n][i] = 0.0f;

    tile_gemm3(sb,
               g_xh + (size_t)(rt * 128) * EMB, g_xl + (size_t)(rt * 128) * EMB,
               g_wt + (size_t)(mat * HEAD) * EMB,
               EMB, EMB, 32, tid, c);

    const int gid = lane >> 2, tig = lane & 3;
    if (mat == 2) {
#pragma unroll
        for (int m = 0; m < 2; m++) {
            const int r = rt * 128 + wm * 32 + m * 16 + gid;
#pragma unroll
            for (int n = 0; n < 8; n++) {
                const int col = wn * 64 + n * 8 + tig * 2;
                *(float2*)(g_v + (size_t)r * HEAD + col)       = make_float2(c[m][n][0], c[m][n][1]);
                *(float2*)(g_v + (size_t)(r + 8) * HEAD + col) = make_float2(c[m][n][2], c[m][n][3]);
            }
        }
    } else {
        ushort_t* Y = (mat == 0) ? g_qh : g_kh;
        const float sc = (mat == 0) ? SCALE : 1.0f;
#pragma unroll
        for (int m = 0; m < 2; m++) {
            const int r = rt * 128 + wm * 32 + m * 16 + gid;
#pragma unroll
            for (int n = 0; n < 8; n++) {
                const int col = wn * 64 + n * 8 + tig * 2;
                *(unsigned*)&Y[(size_t)r * HEAD + col]       = pack_h2(c[m][n][0] * sc, c[m][n][1] * sc);
                *(unsigned*)&Y[(size_t)(r + 8) * HEAD + col] = pack_h2(c[m][n][2] * sc, c[m][n][3] * sc);
            }
        }
    }
}

// ---------------- kernel 2: scores (1-term fp16) --------------------------------
__global__ __launch_bounds__(256, 2) void scores_tc(void) {
    extern __shared__ ushort_t dynS[];
    __shared__ float s_col[128];
    const int tid = threadIdx.x, lane = tid & 31, wid = tid >> 5;
    const int wm = wid & 3, wn = wid >> 2;
    const int b = blockIdx.x / NTRI;
    int qt, kt;
    tri_decode(blockIdx.x % NTRI, qt, kt);
    const uint32_t sb = smem_u32(dynS);

    if (tid < 128) s_col[tid] = 0.0f;

    float c[2][8][4];
#pragma unroll
    for (int m = 0; m < 2; m++)
#pragma unroll
        for (int n = 0; n < 8; n++)
#pragma unroll
            for (int i = 0; i < 4; i++) c[m][n][i] = 0.0f;

    tile_gemm2(sb,
               g_qh + (size_t)(b * SEQ + qt * 128) * HEAD,
               g_kh + (size_t)(b * SEQ + kt * 128) * HEAD,
               HEAD, HEAD, 4, tid, c);

    const int gid = lane >> 2, tig = lane & 3;
    float p0[8], p1[8];
#pragma unroll
    for (int n = 0; n < 8; n++) { p0[n] = 0.0f; p1[n] = 0.0f; }

#pragma unroll
    for (int m = 0; m < 2; m++) {
        const int r   = wm * 32 + m * 16 + gid;
        const int gq0 = qt * 128 + r;
        const int gq1 = gq0 + 8;
#pragma unroll
        for (int n = 0; n < 8; n++) {
            const int cn = wn * 64 + n * 8 + tig * 2;
            const int gk = kt * 128 + cn;
            float e0 = (gq0 >= gk)     ? fast_exp(c[m][n][0]) : 0.0f;
            float e1 = (gq0 >= gk + 1) ? fast_exp(c[m][n][1]) : 0.0f;
            float e2 = (gq1 >= gk)     ? fast_exp(c[m][n][2]) : 0.0f;
            float e3 = (gq1 >= gk + 1) ? fast_exp(c[m][n][3]) : 0.0f;
            p0[n] += e0 + e2;
            p1[n] += e1 + e3;
            *(unsigned*)&g_eh[((size_t)b * SEQ + gq0) * SEQ + gk] = pack_h2(e0, e1);
            *(unsigned*)&g_eh[((size_t)b * SEQ + gq1) * SEQ + gk] = pack_h2(e2, e3);
        }
    }
#pragma unroll
    for (int n = 0; n < 8; n++) {
        p0[n] += __shfl_down_sync(0xffffffff, p0[n], 16);
        p0[n] += __shfl_down_sync(0xffffffff, p0[n], 8);
        p0[n] += __shfl_down_sync(0xffffffff, p0[n], 4);
        p1[n] += __shfl_down_sync(0xffffffff, p1[n], 16);
        p1[n] += __shfl_down_sync(0xffffffff, p1[n], 8);
        p1[n] += __shfl_down_sync(0xffffffff, p1[n], 4);
    }
    if (lane < 4) {
#pragma unroll
        for (int n = 0; n < 8; n++) {
            atomicAdd(&s_col[wn * 64 + n * 8 + lane * 2],     p0[n]);
            atomicAdd(&s_col[wn * 64 + n * 8 + lane * 2 + 1], p1[n]);
        }
    }
    __syncthreads();
    if (tid < 128) atomicAdd(&g_colsum[b * SEQ + kt * 128 + tid], s_col[tid]);
}

// ---------------- kernel 3: vprep — (v*inv)^T fp16 -----------------------------
__global__ __launch_bounds__(256) void vprep_kernel() {
    __shared__ ushort_t sh[128][72];
    const int tid   = threadIdx.x;
    const int batch = blockIdx.x >> 5;
    const int kt64  = blockIdx.x & 31;

    const int r  = tid >> 2;
    const int cb = (tid & 3) * 32;
    const int key = batch * SEQ + kt64 * 64 + r;
    const float inv = 1.0f / g_colsum[key];
    const float* vp = g_v + (size_t)key * HEAD + cb;
#pragma unroll
    for (int j = 0; j < 8; j++) {
        float4 v4 = *(const float4*)(vp + j * 4);
        float v[4] = {v4.x, v4.y, v4.z, v4.w};
#pragma unroll
        for (int i = 0; i < 4; i++) {
            __half h = __float2half_rn(v[i] * inv);
            sh[cb + j * 4 + i][r] = *(ushort_t*)&h;
        }
    }
    __syncthreads();
    const int h  = tid >> 1;
    const int kc = (tid & 1) * 32;
    size_t gbase = (size_t)(batch * HEAD + h) * SEQ + kt64 * 64 + kc;
#pragma unroll
    for (int j = 0; j < 4; j++) {
        uint2 u0 = *(const uint2*)&sh[h][kc + j * 8];
        uint2 u1 = *(const uint2*)&sh[h][kc + j * 8 + 4];
        *(uint4*)&g_vth[gbase + j * 8] = make_uint4(u0.x, u0.y, u1.x, u1.y);
    }
}

// ---------------- kernel 4: out = expS @ v' (1-term fp16) ----------------------
__global__ __launch_bounds__(256, 2) void out_tc(float* __restrict__ out) {
    extern __shared__ ushort_t dynS[];
    const int tid = threadIdx.x, lane = tid & 31, wid = tid >> 5;
    const int wm = wid & 3, wn = wid >> 2;
    const int b = blockIdx.x / NTRI;
    int qt, kt;
    tri_decode(blockIdx.x % NTRI, qt, kt);
    const uint32_t sb = smem_u32(dynS);

    float c[2][8][4];
#pragma unroll
    for (int m = 0; m < 2; m++)
#pragma unroll
        for (int n = 0; n < 8; n++)
#pragma unroll
            for (int i = 0; i < 4; i++) c[m][n][i] = 0.0f;

    tile_gemm2(sb,
               g_eh + ((size_t)b * SEQ + qt * 128) * SEQ + kt * 128,
               g_vth + (size_t)(b * HEAD) * SEQ + kt * 128,
               SEQ, SEQ, 4, tid, c);

    const int gid = lane >> 2, tig = lane & 3;
#pragma unroll
    for (int m = 0; m < 2; m++) {
        const int r = qt * 128 + wm * 32 + m * 16 + gid;
#pragma unroll
        for (int n = 0; n < 8; n++) {
            const int cn = wn * 64 + n * 8 + tig * 2;
            float* op = out + ((size_t)b * SEQ + r) * HEAD + cn;
            atomicAdd(op,     c[m][n][0]);
            atomicAdd(op + 1, c[m][n][1]);
            atomicAdd(op + (size_t)8 * HEAD,     c[m][n][2]);
            atomicAdd(op + (size_t)8 * HEAD + 1, c[m][n][3]);
        }
    }
}

// ---------------- launch --------------------------------------------------------
extern "C" void kernel_launch(void* const* d_in, const int* in_sizes, int n_in,
                              void* d_out, int out_size) {
    const float* X  = (const float*)d_in[0];
    const float* Wq = (const float*)d_in[1];
    const float* Wk = (const float*)d_in[2];
    const float* Wv = (const float*)d_in[3];
    float* out = (float*)d_out;

    const int smem3 = 2 * STAGE3;   // 61440 (qkv)
    const int smem2 = 2 * STAGE2;   // 40960 (scores, out)
    cudaFuncSetAttribute(qkv_tc,    cudaFuncAttributeMaxDynamicSharedMemorySize, smem3);
    cudaFuncSetAttribute(scores_tc, cudaFuncAttributeMaxDynamicSharedMemorySize, smem2);
    cudaFuncSetAttribute(out_tc,    cudaFuncAttributeMaxDynamicSharedMemorySize, smem2);

    zero_kernel<<<(BATCH * SEQ * HEAD + 255) / 256, 256>>>(out);
    prep_x<<<BATCH * SEQ * EMB / 2 / 256, 256>>>(X);
    prep_w<<<3 * HEAD * EMB / 2 / 256, 256>>>(Wq, Wk, Wv);
    qkv_tc<<<dim3(BATCH * SEQ / 128, 3), 256, smem3>>>();
    scores_tc<<<BATCH * NTRI, 256, smem2>>>();
    vprep_kernel<<<BATCH * SEQ / 64, 256>>>();
    out_tc<<<BATCH * NTRI, 256, smem2>>>(out);
}

// round 16
// speedup vs baseline: 1.9125x; 1.2442x over previous
#include <cuda_runtime.h>
#include <cuda_fp16.h>
#include <math.h>
#include <stdint.h>

#define BATCH 8
#define SEQ   2048
#define EMB   1024
#define HEAD  128
#define NTRI  136            // lower-tri 128x128 tiles per batch
#define SCALE 0.03125f       // 1/sqrt(1024)

typedef unsigned short ushort_t;

// Slab = [128][40] ushort = 10240B. Stage = 2 slabs (A, B) = 20480B.
#define SLAB   10240u
#define STAGE  20480u

// ---------------- global scratch (fp16, all single precision operands) ----------
__device__ ushort_t g_x[BATCH * SEQ * EMB];                             // X fp16 [row][emb]
__device__ ushort_t g_wt[3 * HEAD * EMB];                               // W^T fp16 [mat][head][emb]
__device__ ushort_t g_qh[BATCH * SEQ * HEAD];                           // q' fp16 [tok][head]
__device__ ushort_t g_kh[BATCH * SEQ * HEAD];                           // k fp16 [tok][head]
__device__ ushort_t g_vth[BATCH * HEAD * SEQ];                          // (v*inv)^T fp16 [head][key]
__device__ ushort_t g_eh[(size_t)BATCH * SEQ * SEQ];                    // expS fp16, 64MB
__device__ float    g_v[BATCH * SEQ * HEAD];
__device__ float    g_colsum[BATCH * SEQ];

// ---------------- helpers ------------------------------------------------------
__device__ __forceinline__ uint32_t smem_u32(const void* p) {
    uint32_t a;
    asm("{ .reg .u64 t; cvta.to.shared.u64 t, %1; cvt.u32.u64 %0, t; }" : "=r"(a) : "l"(p));
    return a;
}
__device__ __forceinline__ void cpa16(uint32_t dst, const void* src) {
    asm volatile("cp.async.cg.shared.global [%0], [%1], 16;" :: "r"(dst), "l"(src));
}
__device__ __forceinline__ float fast_exp(float x) {
    float r = 2.0876757e-9f;
    r = fmaf(r, x, 2.5052108e-8f);
    r = fmaf(r, x, 2.7557319e-7f);
    r = fmaf(r, x, 2.7557319e-6f);
    r = fmaf(r, x, 2.4801587e-5f);
    r = fmaf(r, x, 1.9841270e-4f);
    r = fmaf(r, x, 1.3888889e-3f);
    r = fmaf(r, x, 8.3333333e-3f);
    r = fmaf(r, x, 4.1666667e-2f);
    r = fmaf(r, x, 1.6666667e-1f);
    r = fmaf(r, x, 0.5f);
    r = fmaf(r, x, 1.0f);
    r = fmaf(r, x, 1.0f);
    if (fabsf(x) > 2.0f) r = __expf(x);
    return r;
}
__device__ __forceinline__ void tri_decode(int t, int& qt, int& kt) {
    int q = (int)((sqrtf(8.0f * (float)t + 1.0f) - 1.0f) * 0.5f);
    while ((q + 1) * (q + 2) / 2 <= t) q++;
    while (q * (q + 1) / 2 > t) q--;
    qt = q;
    kt = t - q * (q + 1) / 2;
}
__device__ __forceinline__ unsigned pack_h2(float a, float b) {
    __half2 h = __floats2half2_rn(a, b);
    return *(unsigned*)&h;
}
__device__ __forceinline__ void mma16816(float c[4], const unsigned a[4], const unsigned b[2]) {
    asm volatile(
        "mma.sync.aligned.m16n8k16.row.col.f32.f16.f16.f32 "
        "{%0,%1,%2,%3}, {%4,%5,%6,%7}, {%8,%9}, {%0,%1,%2,%3};\n"
        : "+f"(c[0]), "+f"(c[1]), "+f"(c[2]), "+f"(c[3])
        : "r"(a[0]), "r"(a[1]), "r"(a[2]), "r"(a[3]), "r"(b[0]), "r"(b[1]));
}
__device__ __forceinline__ void ldsm_x4(unsigned* r, uint32_t a) {
    asm volatile("ldmatrix.sync.aligned.m8n8.x4.shared.b16 {%0,%1,%2,%3}, [%4];"
                 : "=r"(r[0]), "=r"(r[1]), "=r"(r[2]), "=r"(r[3]) : "r"(a));
}

// ---------------- GEMM path: slabs A, B -----------------------------------------
__device__ __forceinline__ void stage_issue2(
    uint32_t base, const ushort_t* A, const ushort_t* Bh,
    size_t strideA, size_t strideB, int k0, int r0, int seg) {
    const uint32_t ro = (uint32_t)r0 * 80u + (uint32_t)seg * 2u;
    cpa16(base + ro,                A + (size_t)r0 * strideA + k0 + seg);
    cpa16(base + ro + 5120u,        A + (size_t)(r0 + 64) * strideA + k0 + seg);
    cpa16(base + SLAB + ro,         Bh + (size_t)r0 * strideB + k0 + seg);
    cpa16(base + SLAB + ro + 5120u, Bh + (size_t)(r0 + 64) * strideB + k0 + seg);
    asm volatile("cp.async.commit_group;");
}

__device__ __forceinline__ void chunk_mma2(uint32_t base, int lane, int wm, int wn,
                                           float c[2][8][4]) {
    const uint32_t aAddr = base + (uint32_t)(wm * 32 + (lane & 15)) * 80u + ((lane >> 4) * 8u) * 2u;
    const uint32_t bAddr = base + SLAB
                         + (uint32_t)(wn * 64 + (lane & 7) + (((lane >> 4) & 1) * 8)) * 80u
                         + (((lane >> 3) & 1) * 8u) * 2u;
#pragma unroll
    for (int kh = 0; kh < 2; kh++) {
        const uint32_t ko = kh * 32u;
        unsigned ah[2][4];
        ldsm_x4(ah[0], aAddr + ko);
        ldsm_x4(ah[1], aAddr + 1280u + ko);
#pragma unroll
        for (int j = 0; j < 4; j++) {
            unsigned bh4[4];
            ldsm_x4(bh4, bAddr + (uint32_t)j * 1280u + ko);
#pragma unroll
            for (int nn = 0; nn < 2; nn++) {
                unsigned b2[2] = {bh4[nn * 2], bh4[nn * 2 + 1]};
                mma16816(c[0][j * 2 + nn], ah[0], b2);
                mma16816(c[1][j * 2 + nn], ah[1], b2);
            }
        }
    }
}

__device__ __forceinline__ void tile_gemm2(
    uint32_t sb, const ushort_t* A, const ushort_t* Bh,
    size_t strideA, size_t strideB, int NC, int tid, float c[2][8][4]) {
    const int lane = tid & 31, wid = tid >> 5;
    const int wm = wid & 3, wn = wid >> 2;
    const int r0 = tid >> 2, seg = (tid & 3) * 8;

    stage_issue2(sb, A, Bh, strideA, strideB, 0, r0, seg);
    for (int kc = 0; kc < NC; kc++) {
        const int s = kc & 1;
        if (kc + 1 < NC) {
            stage_issue2(sb + (uint32_t)(s ^ 1) * STAGE, A, Bh,
                         strideA, strideB, (kc + 1) * 32, r0, seg);
            asm volatile("cp.async.wait_group 1;");
        } else {
            asm volatile("cp.async.wait_group 0;");
        }
        __syncthreads();
        chunk_mma2(sb + (uint32_t)s * STAGE, lane, wm, wn, c);
        __syncthreads();
    }
}

// ---------------- kernel 0: zero -----------------------------------------------
__global__ void zero_kernel(float* __restrict__ out) {
    int i = blockIdx.x * blockDim.x + threadIdx.x;
    if (i < BATCH * SEQ * HEAD) out[i] = 0.0f;
    if (i < BATCH * SEQ) g_colsum[i] = 0.0f;
}

// ---------------- prep: X single fp16 -------------------------------------------
__global__ __launch_bounds__(256) void prep_x(const float* __restrict__ X) {
    int p = blockIdx.x * 256 + threadIdx.x;
    int row = p >> 9, kp = (p & 511) * 2;
    float2 v = *(const float2*)(X + (size_t)row * EMB + kp);
    *(unsigned*)&g_x[(size_t)row * EMB + kp] = pack_h2(v.x, v.y);
}

// ---------------- prep: W^T single fp16 -----------------------------------------
__global__ __launch_bounds__(256) void prep_w(const float* __restrict__ Wq,
                                              const float* __restrict__ Wk,
                                              const float* __restrict__ Wv) {
    int p = blockIdx.x * 256 + threadIdx.x;
    int mat = p >> 16;
    int rem = p & 65535;
    int n = rem >> 9, kp = (rem & 511) * 2;
    const float* W = (mat == 0) ? Wq : (mat == 1) ? Wk : Wv;
    float v0 = W[(size_t)kp * HEAD + n];
    float v1 = W[(size_t)(kp + 1) * HEAD + n];
    *(unsigned*)&g_wt[(size_t)(mat * HEAD + n) * EMB + kp] = pack_h2(v0, v1);
}

// ---------------- kernel 1: QKV (1-term fp16) -----------------------------------
__global__ __launch_bounds__(256, 2) void qkv_tc(void) {
    extern __shared__ ushort_t dynS[];
    const int tid = threadIdx.x, lane = tid & 31, wid = tid >> 5;
    const int wm = wid & 3, wn = wid >> 2;
    const int rt = blockIdx.x, mat = blockIdx.y;
    const uint32_t sb = smem_u32(dynS);

    float c[2][8][4];
#pragma unroll
    for (int m = 0; m < 2; m++)
#pragma unroll
        for (int n = 0; n < 8; n++)
#pragma unroll
            for (int i = 0; i < 4; i++) c[m][n][i] = 0.0f;

    tile_gemm2(sb,
               g_x + (size_t)(rt * 128) * EMB,
               g_wt + (size_t)(mat * HEAD) * EMB,
               EMB, EMB, 32, tid, c);

    const int gid = lane >> 2, tig = lane & 3;
    if (mat == 2) {
#pragma unroll
        for (int m = 0; m < 2; m++) {
            const int r = rt * 128 + wm * 32 + m * 16 + gid;
#pragma unroll
            for (int n = 0; n < 8; n++) {
                const int col = wn * 64 + n * 8 + tig * 2;
                *(float2*)(g_v + (size_t)r * HEAD + col)       = make_float2(c[m][n][0], c[m][n][1]);
                *(float2*)(g_v + (size_t)(r + 8) * HEAD + col) = make_float2(c[m][n][2], c[m][n][3]);
            }
        }
    } else {
        ushort_t* Y = (mat == 0) ? g_qh : g_kh;
        const float sc = (mat == 0) ? SCALE : 1.0f;
#pragma unroll
        for (int m = 0; m < 2; m++) {
            const int r = rt * 128 + wm * 32 + m * 16 + gid;
#pragma unroll
            for (int n = 0; n < 8; n++) {
                const int col = wn * 64 + n * 8 + tig * 2;
                *(unsigned*)&Y[(size_t)r * HEAD + col]       = pack_h2(c[m][n][0] * sc, c[m][n][1] * sc);
                *(unsigned*)&Y[(size_t)(r + 8) * HEAD + col] = pack_h2(c[m][n][2] * sc, c[m][n][3] * sc);
            }
        }
    }
}

// ---------------- kernel 2: scores (1-term fp16) --------------------------------
__global__ __launch_bounds__(256, 2) void scores_tc(void) {
    extern __shared__ ushort_t dynS[];
    __shared__ float s_col[128];
    const int tid = threadIdx.x, lane = tid & 31, wid = tid >> 5;
    const int wm = wid & 3, wn = wid >> 2;
    const int b = blockIdx.x / NTRI;
    int qt, kt;
    tri_decode(blockIdx.x % NTRI, qt, kt);
    const uint32_t sb = smem_u32(dynS);

    if (tid < 128) s_col[tid] = 0.0f;

    float c[2][8][4];
#pragma unroll
    for (int m = 0; m < 2; m++)
#pragma unroll
        for (int n = 0; n < 8; n++)
#pragma unroll
            for (int i = 0; i < 4; i++) c[m][n][i] = 0.0f;

    tile_gemm2(sb,
               g_qh + (size_t)(b * SEQ + qt * 128) * HEAD,
               g_kh + (size_t)(b * SEQ + kt * 128) * HEAD,
               HEAD, HEAD, 4, tid, c);

    const int gid = lane >> 2, tig = lane & 3;
    float p0[8], p1[8];
#pragma unroll
    for (int n = 0; n < 8; n++) { p0[n] = 0.0f; p1[n] = 0.0f; }

#pragma unroll
    for (int m = 0; m < 2; m++) {
        const int r   = wm * 32 + m * 16 + gid;
        const int gq0 = qt * 128 + r;
        const int gq1 = gq0 + 8;
#pragma unroll
        for (int n = 0; n < 8; n++) {
            const int cn = wn * 64 + n * 8 + tig * 2;
            const int gk = kt * 128 + cn;
            float e0 = (gq0 >= gk)     ? fast_exp(c[m][n][0]) : 0.0f;
            float e1 = (gq0 >= gk + 1) ? fast_exp(c[m][n][1]) : 0.0f;
            float e2 = (gq1 >= gk)     ? fast_exp(c[m][n][2]) : 0.0f;
            float e3 = (gq1 >= gk + 1) ? fast_exp(c[m][n][3]) : 0.0f;
            p0[n] += e0 + e2;
            p1[n] += e1 + e3;
            *(unsigned*)&g_eh[((size_t)b * SEQ + gq0) * SEQ + gk] = pack_h2(e0, e1);
            *(unsigned*)&g_eh[((size_t)b * SEQ + gq1) * SEQ + gk] = pack_h2(e2, e3);
        }
    }
#pragma unroll
    for (int n = 0; n < 8; n++) {
        p0[n] += __shfl_down_sync(0xffffffff, p0[n], 16);
        p0[n] += __shfl_down_sync(0xffffffff, p0[n], 8);
        p0[n] += __shfl_down_sync(0xffffffff, p0[n], 4);
        p1[n] += __shfl_down_sync(0xffffffff, p1[n], 16);
        p1[n] += __shfl_down_sync(0xffffffff, p1[n], 8);
        p1[n] += __shfl_down_sync(0xffffffff, p1[n], 4);
    }
    if (lane < 4) {
#pragma unroll
        for (int n = 0; n < 8; n++) {
            atomicAdd(&s_col[wn * 64 + n * 8 + lane * 2],     p0[n]);
            atomicAdd(&s_col[wn * 64 + n * 8 + lane * 2 + 1], p1[n]);
        }
    }
    __syncthreads();
    if (tid < 128) atomicAdd(&g_colsum[b * SEQ + kt * 128 + tid], s_col[tid]);
}

// ---------------- kernel 3: vprep — (v*inv)^T fp16 -----------------------------
__global__ __launch_bounds__(256) void vprep_kernel() {
    __shared__ ushort_t sh[128][72];
    const int tid   = threadIdx.x;
    const int batch = blockIdx.x >> 5;
    const int kt64  = blockIdx.x & 31;

    const int r  = tid >> 2;
    const int cb = (tid & 3) * 32;
    const int key = batch * SEQ + kt64 * 64 + r;
    const float inv = 1.0f / g_colsum[key];
    const float* vp = g_v + (size_t)key * HEAD + cb;
#pragma unroll
    for (int j = 0; j < 8; j++) {
        float4 v4 = *(const float4*)(vp + j * 4);
        float v[4] = {v4.x, v4.y, v4.z, v4.w};
#pragma unroll
        for (int i = 0; i < 4; i++) {
            __half h = __float2half_rn(v[i] * inv);
            sh[cb + j * 4 + i][r] = *(ushort_t*)&h;
        }
    }
    __syncthreads();
    const int h  = tid >> 1;
    const int kc = (tid & 1) * 32;
    size_t gbase = (size_t)(batch * HEAD + h) * SEQ + kt64 * 64 + kc;
#pragma unroll
    for (int j = 0; j < 4; j++) {
        uint2 u0 = *(const uint2*)&sh[h][kc + j * 8];
        uint2 u1 = *(const uint2*)&sh[h][kc + j * 8 + 4];
        *(uint4*)&g_vth[gbase + j * 8] = make_uint4(u0.x, u0.y, u1.x, u1.y);
    }
}

// ---------------- kernel 4: out = expS @ v' (1-term fp16) ----------------------
__global__ __launch_bounds__(256, 2) void out_tc(float* __restrict__ out) {
    extern __shared__ ushort_t dynS[];
    const int tid = threadIdx.x, lane = tid & 31, wid = tid >> 5;
    const int wm = wid & 3, wn = wid >> 2;
    const int b = blockIdx.x / NTRI;
    int qt, kt;
    tri_decode(blockIdx.x % NTRI, qt, kt);
    const uint32_t sb = smem_u32(dynS);

    float c[2][8][4];
#pragma unroll
    for (int m = 0; m < 2; m++)
#pragma unroll
        for (int n = 0; n < 8; n++)
#pragma unroll
            for (int i = 0; i < 4; i++) c[m][n][i] = 0.0f;

    tile_gemm2(sb,
               g_eh + ((size_t)b * SEQ + qt * 128) * SEQ + kt * 128,
               g_vth + (size_t)(b * HEAD) * SEQ + kt * 128,
               SEQ, SEQ, 4, tid, c);

    const int gid = lane >> 2, tig = lane & 3;
#pragma unroll
    for (int m = 0; m < 2; m++) {
        const int r = qt * 128 + wm * 32 + m * 16 + gid;
#pragma unroll
        for (int n = 0; n < 8; n++) {
            const int cn = wn * 64 + n * 8 + tig * 2;
            float* op = out + ((size_t)b * SEQ + r) * HEAD + cn;
            atomicAdd(op,     c[m][n][0]);
            atomicAdd(op + 1, c[m][n][1]);
            atomicAdd(op + (size_t)8 * HEAD,     c[m][n][2]);
            atomicAdd(op + (size_t)8 * HEAD + 1, c[m][n][3]);
        }
    }
}

// ---------------- launch --------------------------------------------------------
extern "C" void kernel_launch(void* const* d_in, const int* in_sizes, int n_in,
                              void* d_out, int out_size) {
    const float* X  = (const float*)d_in[0];
    const float* Wq = (const float*)d_in[1];
    const float* Wk = (const float*)d_in[2];
    const float* Wv = (const float*)d_in[3];
    float* out = (float*)d_out;

    const int smem = 2 * STAGE;   // 40960
    cudaFuncSetAttribute(qkv_tc,    cudaFuncAttributeMaxDynamicSharedMemorySize, smem);
    cudaFuncSetAttribute(scores_tc, cudaFuncAttributeMaxDynamicSharedMemorySize, smem);
    cudaFuncSetAttribute(out_tc,    cudaFuncAttributeMaxDynamicSharedMemorySize, smem);

    zero_kernel<<<(BATCH * SEQ * HEAD + 255) / 256, 256>>>(out);
    prep_x<<<BATCH * SEQ * EMB / 2 / 256, 256>>>(X);
    prep_w<<<3 * HEAD * EMB / 2 / 256, 256>>>(Wq, Wk, Wv);
    qkv_tc<<<dim3(BATCH * SEQ / 128, 3), 256, smem>>>();
    scores_tc<<<BATCH * NTRI, 256, smem>>>();
    vprep_kernel<<<BATCH * SEQ / 64, 256>>>();
    out_tc<<<BATCH * NTRI, 256, smem>>>(out);
}

// round 17
// speedup vs baseline: 2.0495x; 1.0716x over previous
#include <cuda_runtime.h>
#include <cuda_fp16.h>
#include <math.h>
#include <stdint.h>

#define BATCH 8
#define SEQ   2048
#define EMB   1024
#define HEAD  128
#define NTRI  136            // lower-tri 128x128 tiles per batch
#define SCALE 0.03125f       // 1/sqrt(1024)

typedef unsigned short ushort_t;

// M128 GEMM stage: 2 slabs [128][40] ushort = 10240B each; stage = 20480B.
#define SLAB   10240u
#define STAGE  20480u
// M64 out-GEMM stage: A slab [64][40] = 5120B + B slab [128][40] = 10240B; stage = 15360B.
#define SLAB_A64 5120u
#define STAGE_O  15360u

// ---------------- global scratch (fp16 single-precision operands) ---------------
__device__ ushort_t g_x[BATCH * SEQ * EMB];                             // X fp16 [row][emb]
__device__ ushort_t g_wt[3 * HEAD * EMB];                               // W^T fp16 [mat][head][emb]
__device__ ushort_t g_qh[BATCH * SEQ * HEAD];                           // q' fp16 [tok][head]
__device__ ushort_t g_kh[BATCH * SEQ * HEAD];                           // k fp16 [tok][head]
__device__ ushort_t g_vth[BATCH * HEAD * SEQ];                          // (v*inv)^T fp16 [head][key]
__device__ ushort_t g_eh[(size_t)BATCH * SEQ * SEQ];                    // expS fp16, 64MB
__device__ float    g_v[BATCH * SEQ * HEAD];
__device__ float    g_colsum[BATCH * SEQ];

// ---------------- helpers ------------------------------------------------------
__device__ __forceinline__ uint32_t smem_u32(const void* p) {
    uint32_t a;
    asm("{ .reg .u64 t; cvta.to.shared.u64 t, %1; cvt.u32.u64 %0, t; }" : "=r"(a) : "l"(p));
    return a;
}
__device__ __forceinline__ void cpa16(uint32_t dst, const void* src) {
    asm volatile("cp.async.cg.shared.global [%0], [%1], 16;" :: "r"(dst), "l"(src));
}
__device__ __forceinline__ void tri_decode(int t, int& qt, int& kt) {
    int q = (int)((sqrtf(8.0f * (float)t + 1.0f) - 1.0f) * 0.5f);
    while ((q + 1) * (q + 2) / 2 <= t) q++;
    while (q * (q + 1) / 2 > t) q--;
    qt = q;
    kt = t - q * (q + 1) / 2;
}
__device__ __forceinline__ unsigned pack_h2(float a, float b) {
    __half2 h = __floats2half2_rn(a, b);
    return *(unsigned*)&h;
}
__device__ __forceinline__ void mma16816(float c[4], const unsigned a[4], const unsigned b[2]) {
    asm volatile(
        "mma.sync.aligned.m16n8k16.row.col.f32.f16.f16.f32 "
        "{%0,%1,%2,%3}, {%4,%5,%6,%7}, {%8,%9}, {%0,%1,%2,%3};\n"
        : "+f"(c[0]), "+f"(c[1]), "+f"(c[2]), "+f"(c[3])
        : "r"(a[0]), "r"(a[1]), "r"(a[2]), "r"(a[3]), "r"(b[0]), "r"(b[1]));
}
__device__ __forceinline__ void ldsm_x4(unsigned* r, uint32_t a) {
    asm volatile("ldmatrix.sync.aligned.m8n8.x4.shared.b16 {%0,%1,%2,%3}, [%4];"
                 : "=r"(r[0]), "=r"(r[1]), "=r"(r[2]), "=r"(r[3]) : "r"(a));
}

// ---------------- M128 GEMM path (qkv, scores) ----------------------------------
__device__ __forceinline__ void stage_issue2(
    uint32_t base, const ushort_t* A, const ushort_t* Bh,
    size_t strideA, size_t strideB, int k0, int r0, int seg) {
    const uint32_t ro = (uint32_t)r0 * 80u + (uint32_t)seg * 2u;
    cpa16(base + ro,                A + (size_t)r0 * strideA + k0 + seg);
    cpa16(base + ro + 5120u,        A + (size_t)(r0 + 64) * strideA + k0 + seg);
    cpa16(base + SLAB + ro,         Bh + (size_t)r0 * strideB + k0 + seg);
    cpa16(base + SLAB + ro + 5120u, Bh + (size_t)(r0 + 64) * strideB + k0 + seg);
    asm volatile("cp.async.commit_group;");
}

__device__ __forceinline__ void chunk_mma2(uint32_t base, int lane, int wm, int wn,
                                           float c[2][8][4]) {
    const uint32_t aAddr = base + (uint32_t)(wm * 32 + (lane & 15)) * 80u + ((lane >> 4) * 8u) * 2u;
    const uint32_t bAddr = base + SLAB
                         + (uint32_t)(wn * 64 + (lane & 7) + (((lane >> 4) & 1) * 8)) * 80u
                         + (((lane >> 3) & 1) * 8u) * 2u;
#pragma unroll
    for (int kh = 0; kh < 2; kh++) {
        const uint32_t ko = kh * 32u;
        unsigned ah[2][4];
        ldsm_x4(ah[0], aAddr + ko);
        ldsm_x4(ah[1], aAddr + 1280u + ko);
#pragma unroll
        for (int j = 0; j < 4; j++) {
            unsigned bh4[4];
            ldsm_x4(bh4, bAddr + (uint32_t)j * 1280u + ko);
#pragma unroll
            for (int nn = 0; nn < 2; nn++) {
                unsigned b2[2] = {bh4[nn * 2], bh4[nn * 2 + 1]};
                mma16816(c[0][j * 2 + nn], ah[0], b2);
                mma16816(c[1][j * 2 + nn], ah[1], b2);
            }
        }
    }
}

__device__ __forceinline__ void tile_gemm2(
    uint32_t sb, const ushort_t* A, const ushort_t* Bh,
    size_t strideA, size_t strideB, int NC, int tid, float c[2][8][4]) {
    const int lane = tid & 31, wid = tid >> 5;
    const int wm = wid & 3, wn = wid >> 2;
    const int r0 = tid >> 2, seg = (tid & 3) * 8;

    stage_issue2(sb, A, Bh, strideA, strideB, 0, r0, seg);
    for (int kc = 0; kc < NC; kc++) {
        const int s = kc & 1;
        if (kc + 1 < NC) {
            stage_issue2(sb + (uint32_t)(s ^ 1) * STAGE, A, Bh,
                         strideA, strideB, (kc + 1) * 32, r0, seg);
            asm volatile("cp.async.wait_group 1;");
        } else {
            asm volatile("cp.async.wait_group 0;");
        }
        __syncthreads();
        chunk_mma2(sb + (uint32_t)s * STAGE, lane, wm, wn, c);
        __syncthreads();
    }
}

// ---------------- M64 GEMM path (out) -------------------------------------------
__device__ __forceinline__ void stage_issue_o(
    uint32_t base, const ushort_t* A, const ushort_t* Bh,
    size_t strideA, size_t strideB, int k0, int r0, int seg) {
    const uint32_t ro = (uint32_t)r0 * 80u + (uint32_t)seg * 2u;
    cpa16(base + ro,                           A + (size_t)r0 * strideA + k0 + seg);       // A rows 0..63
    cpa16(base + SLAB_A64 + ro,                Bh + (size_t)r0 * strideB + k0 + seg);      // B rows 0..63
    cpa16(base + SLAB_A64 + ro + 5120u,        Bh + (size_t)(r0 + 64) * strideB + k0 + seg); // B rows 64..127
    asm volatile("cp.async.commit_group;");
}

__device__ __forceinline__ void chunk_mma_o(uint32_t base, int lane, int wm, int wn,
                                            float c[2][4][4]) {
    const uint32_t aAddr = base + (uint32_t)(wm * 32 + (lane & 15)) * 80u + ((lane >> 4) * 8u) * 2u;
    const uint32_t bAddr = base + SLAB_A64
                         + (uint32_t)(wn * 32 + (lane & 7) + (((lane >> 4) & 1) * 8)) * 80u
                         + (((lane >> 3) & 1) * 8u) * 2u;
#pragma unroll
    for (int kh = 0; kh < 2; kh++) {
        const uint32_t ko = kh * 32u;
        unsigned ah[2][4];
        ldsm_x4(ah[0], aAddr + ko);
        ldsm_x4(ah[1], aAddr + 1280u + ko);
#pragma unroll
        for (int j = 0; j < 2; j++) {
            unsigned bh4[4];
            ldsm_x4(bh4, bAddr + (uint32_t)j * 1280u + ko);
#pragma unroll
            for (int nn = 0; nn < 2; nn++) {
                unsigned b2[2] = {bh4[nn * 2], bh4[nn * 2 + 1]};
                mma16816(c[0][j * 2 + nn], ah[0], b2);
                mma16816(c[1][j * 2 + nn], ah[1], b2);
            }
        }
    }
}

// ---------------- kernel 0: zero colsum -----------------------------------------
__global__ void zero_kernel() {
    int i = blockIdx.x * blockDim.x + threadIdx.x;
    if (i < BATCH * SEQ) g_colsum[i] = 0.0f;
}

// ---------------- prep: X single fp16 -------------------------------------------
__global__ __launch_bounds__(256) void prep_x(const float* __restrict__ X) {
    int p = blockIdx.x * 256 + threadIdx.x;
    int row = p >> 9, kp = (p & 511) * 2;
    float2 v = *(const float2*)(X + (size_t)row * EMB + kp);
    *(unsigned*)&g_x[(size_t)row * EMB + kp] = pack_h2(v.x, v.y);
}

// ---------------- prep: W^T single fp16 -----------------------------------------
__global__ __launch_bounds__(256) void prep_w(const float* __restrict__ Wq,
                                              const float* __restrict__ Wk,
                                              const float* __restrict__ Wv) {
    int p = blockIdx.x * 256 + threadIdx.x;
    int mat = p >> 16;
    int rem = p & 65535;
    int n = rem >> 9, kp = (rem & 511) * 2;
    const float* W = (mat == 0) ? Wq : (mat == 1) ? Wk : Wv;
    float v0 = W[(size_t)kp * HEAD + n];
    float v1 = W[(size_t)(kp + 1) * HEAD + n];
    *(unsigned*)&g_wt[(size_t)(mat * HEAD + n) * EMB + kp] = pack_h2(v0, v1);
}

// ---------------- kernel 1: QKV (1-term fp16) -----------------------------------
__global__ __launch_bounds__(256, 2) void qkv_tc(void) {
    extern __shared__ ushort_t dynS[];
    const int tid = threadIdx.x, lane = tid & 31, wid = tid >> 5;
    const int wm = wid & 3, wn = wid >> 2;
    const int rt = blockIdx.x, mat = blockIdx.y;
    const uint32_t sb = smem_u32(dynS);

    float c[2][8][4];
#pragma unroll
    for (int m = 0; m < 2; m++)
#pragma unroll
        for (int n = 0; n < 8; n++)
#pragma unroll
            for (int i = 0; i < 4; i++) c[m][n][i] = 0.0f;

    tile_gemm2(sb,
               g_x + (size_t)(rt * 128) * EMB,
               g_wt + (size_t)(mat * HEAD) * EMB,
               EMB, EMB, 32, tid, c);

    const int gid = lane >> 2, tig = lane & 3;
    if (mat == 2) {
#pragma unroll
        for (int m = 0; m < 2; m++) {
            const int r = rt * 128 + wm * 32 + m * 16 + gid;
#pragma unroll
            for (int n = 0; n < 8; n++) {
                const int col = wn * 64 + n * 8 + tig * 2;
                *(float2*)(g_v + (size_t)r * HEAD + col)       = make_float2(c[m][n][0], c[m][n][1]);
                *(float2*)(g_v + (size_t)(r + 8) * HEAD + col) = make_float2(c[m][n][2], c[m][n][3]);
            }
        }
    } else {
        ushort_t* Y = (mat == 0) ? g_qh : g_kh;
        const float sc = (mat == 0) ? SCALE : 1.0f;
#pragma unroll
        for (int m = 0; m < 2; m++) {
            const int r = rt * 128 + wm * 32 + m * 16 + gid;
#pragma unroll
            for (int n = 0; n < 8; n++) {
                const int col = wn * 64 + n * 8 + tig * 2;
                *(unsigned*)&Y[(size_t)r * HEAD + col]       = pack_h2(c[m][n][0] * sc, c[m][n][1] * sc);
                *(unsigned*)&Y[(size_t)(r + 8) * HEAD + col] = pack_h2(c[m][n][2] * sc, c[m][n][3] * sc);
            }
        }
    }
}

// ---------------- kernel 2: scores (1-term fp16, MUFU exp) ----------------------
__global__ __launch_bounds__(256, 2) void scores_tc(void) {
    extern __shared__ ushort_t dynS[];
    __shared__ float s_col[128];
    const int tid = threadIdx.x, lane = tid & 31, wid = tid >> 5;
    const int wm = wid & 3, wn = wid >> 2;
    const int b = blockIdx.x / NTRI;
    int qt, kt;
    tri_decode(blockIdx.x % NTRI, qt, kt);
    const uint32_t sb = smem_u32(dynS);

    if (tid < 128) s_col[tid] = 0.0f;

    float c[2][8][4];
#pragma unroll
    for (int m = 0; m < 2; m++)
#pragma unroll
        for (int n = 0; n < 8; n++)
#pragma unroll
            for (int i = 0; i < 4; i++) c[m][n][i] = 0.0f;

    tile_gemm2(sb,
               g_qh + (size_t)(b * SEQ + qt * 128) * HEAD,
               g_kh + (size_t)(b * SEQ + kt * 128) * HEAD,
               HEAD, HEAD, 4, tid, c);

    const int gid = lane >> 2, tig = lane & 3;
    float p0[8], p1[8];
#pragma unroll
    for (int n = 0; n < 8; n++) { p0[n] = 0.0f; p1[n] = 0.0f; }

#pragma unroll
    for (int m = 0; m < 2; m++) {
        const int r   = wm * 32 + m * 16 + gid;
        const int gq0 = qt * 128 + r;
        const int gq1 = gq0 + 8;
#pragma unroll
        for (int n = 0; n < 8; n++) {
            const int cn = wn * 64 + n * 8 + tig * 2;
            const int gk = kt * 128 + cn;
            float e0 = (gq0 >= gk)     ? __expf(c[m][n][0]) : 0.0f;
            float e1 = (gq0 >= gk + 1) ? __expf(c[m][n][1]) : 0.0f;
            float e2 = (gq1 >= gk)     ? __expf(c[m][n][2]) : 0.0f;
            float e3 = (gq1 >= gk + 1) ? __expf(c[m][n][3]) : 0.0f;
            p0[n] += e0 + e2;
            p1[n] += e1 + e3;
            *(unsigned*)&g_eh[((size_t)b * SEQ + gq0) * SEQ + gk] = pack_h2(e0, e1);
            *(unsigned*)&g_eh[((size_t)b * SEQ + gq1) * SEQ + gk] = pack_h2(e2, e3);
        }
    }
#pragma unroll
    for (int n = 0; n < 8; n++) {
        p0[n] += __shfl_down_sync(0xffffffff, p0[n], 16);
        p0[n] += __shfl_down_sync(0xffffffff, p0[n], 8);
        p0[n] += __shfl_down_sync(0xffffffff, p0[n], 4);
        p1[n] += __shfl_down_sync(0xffffffff, p1[n], 16);
        p1[n] += __shfl_down_sync(0xffffffff, p1[n], 8);
        p1[n] += __shfl_down_sync(0xffffffff, p1[n], 4);
    }
    if (lane < 4) {
#pragma unroll
        for (int n = 0; n < 8; n++) {
            atomicAdd(&s_col[wn * 64 + n * 8 + lane * 2],     p0[n]);
            atomicAdd(&s_col[wn * 64 + n * 8 + lane * 2 + 1], p1[n]);
        }
    }
    __syncthreads();
    if (tid < 128) atomicAdd(&g_colsum[b * SEQ + kt * 128 + tid], s_col[tid]);
}

// ---------------- kernel 3: vprep — (v*inv)^T fp16 -----------------------------
__global__ __launch_bounds__(256) void vprep_kernel() {
    __shared__ ushort_t sh[128][72];
    const int tid   = threadIdx.x;
    const int batch = blockIdx.x >> 5;
    const int kt64  = blockIdx.x & 31;

    const int r  = tid >> 2;
    const int cb = (tid & 3) * 32;
    const int key = batch * SEQ + kt64 * 64 + r;
    const float inv = 1.0f / g_colsum[key];
    const float* vp = g_v + (size_t)key * HEAD + cb;
#pragma unroll
    for (int j = 0; j < 8; j++) {
        float4 v4 = *(const float4*)(vp + j * 4);
        float v[4] = {v4.x, v4.y, v4.z, v4.w};
#pragma unroll
        for (int i = 0; i < 4; i++) {
            __half h = __float2half_rn(v[i] * inv);
            sh[cb + j * 4 + i][r] = *(ushort_t*)&h;
        }
    }
    __syncthreads();
    const int h  = tid >> 1;
    const int kc = (tid & 1) * 32;
    size_t gbase = (size_t)(batch * HEAD + h) * SEQ + kt64 * 64 + kc;
#pragma unroll
    for (int j = 0; j < 4; j++) {
        uint2 u0 = *(const uint2*)&sh[h][kc + j * 8];
        uint2 u1 = *(const uint2*)&sh[h][kc + j * 8 + 4];
        *(uint4*)&g_vth[gbase + j * 8] = make_uint4(u0.x, u0.y, u1.x, u1.y);
    }
}

// ---------------- kernel 4: out — atomic-free, per-row-block K accumulation -----
// Grid: 256 CTAs. id -> qt descending (longest first), b, msub.
// CTA owns rows [qt*128 + msub*64, +64), all heads; loops K over kt=0..qt.
__global__ __launch_bounds__(256, 2) void out_tc(float* __restrict__ out) {
    extern __shared__ ushort_t dynS[];
    const int tid = threadIdx.x, lane = tid & 31, wid = tid >> 5;
    const int wm = wid & 1, wn = wid >> 1;
    const int id = blockIdx.x;
    const int qt = 15 - (id >> 4);
    const int b = (id & 15) >> 1;
    const int msub = id & 1;
    const uint32_t sb = smem_u32(dynS);
    const int r0 = tid >> 2, seg = (tid & 3) * 8;

    float c[2][4][4];
#pragma unroll
    for (int m = 0; m < 2; m++)
#pragma unroll
        for (int n = 0; n < 4; n++)
#pragma unroll
            for (int i = 0; i < 4; i++) c[m][n][i] = 0.0f;

    const ushort_t* A = g_eh + ((size_t)b * SEQ + qt * 128 + msub * 64) * SEQ;
    const ushort_t* B = g_vth + (size_t)(b * HEAD) * SEQ;
    const int NC = (qt + 1) * 4;

    stage_issue_o(sb, A, B, SEQ, SEQ, 0, r0, seg);
    for (int kc = 0; kc < NC; kc++) {
        const int s = kc & 1;
        if (kc + 1 < NC) {
            stage_issue_o(sb + (uint32_t)(s ^ 1) * STAGE_O, A, B, SEQ, SEQ, (kc + 1) * 32, r0, seg);
            asm volatile("cp.async.wait_group 1;");
        } else {
            asm volatile("cp.async.wait_group 0;");
        }
        __syncthreads();
        chunk_mma_o(sb + (uint32_t)s * STAGE_O, lane, wm, wn, c);
        __syncthreads();
    }

    const int gid = lane >> 2, tig = lane & 3;
#pragma unroll
    for (int m = 0; m < 2; m++) {
        const int r = qt * 128 + msub * 64 + wm * 32 + m * 16 + gid;
#pragma unroll
        for (int n = 0; n < 4; n++) {
            const int cn = wn * 32 + n * 8 + tig * 2;
            float* op = out + ((size_t)b * SEQ + r) * HEAD + cn;
            *(float2*)op                      = make_float2(c[m][n][0], c[m][n][1]);
            *(float2*)(op + (size_t)8 * HEAD) = make_float2(c[m][n][2], c[m][n][3]);
        }
    }
}

// ---------------- launch --------------------------------------------------------
extern "C" void kernel_launch(void* const* d_in, const int* in_sizes, int n_in,
                              void* d_out, int out_size) {
    const float* X  = (const float*)d_in[0];
    const float* Wq = (const float*)d_in[1];
    const float* Wk = (const float*)d_in[2];
    const float* Wv = (const float*)d_in[3];
    float* out = (float*)d_out;

    const int smem  = 2 * STAGE;    // 40960 (qkv, scores)
    const int smemO = 2 * STAGE_O;  // 30720 (out)
    cudaFuncSetAttribute(qkv_tc,    cudaFuncAttributeMaxDynamicSharedMemorySize, smem);
    cudaFuncSetAttribute(scores_tc, cudaFuncAttributeMaxDynamicSharedMemorySize, smem);
    cudaFuncSetAttribute(out_tc,    cudaFuncAttributeMaxDynamicSharedMemorySize, smemO);

    zero_kernel<<<(BATCH * SEQ + 255) / 256, 256>>>();
    prep_x<<<BATCH * SEQ * EMB / 2 / 256, 256>>>(X);
    prep_w<<<3 * HEAD * EMB / 2 / 256, 256>>>(Wq, Wk, Wv);
    qkv_tc<<<dim3(BATCH * SEQ / 128, 3), 256, smem>>>();
    scores_tc<<<BATCH * NTRI, 256, smem>>>();
    vprep_kernel<<<BATCH * SEQ / 64, 256>>>();
    out_tc<<<256, 256, smemO>>>(out);
}